// round 10
// baseline (speedup 1.0000x reference)
#include <cuda_runtime.h>
#include <cuda_fp16.h>
#include <cstdint>

#define D    128
#define DE   32
#define NET  5
#define MAXN 50000
#define CAP_TOTAL 4000000
#define KW   (D + DE)       // 160

// ---- scratch (device globals: allocation-free; bss zero-init at load) ----
__device__ __half g_xh [(size_t)MAXN * D];            // fp16 op_feats
__device__ __half g_S1h[(size_t)NET * MAXN * D];      // fp16 per-etype mean of src feats
__device__ __half g_S2h[(size_t)NET * MAXN * DE];     // fp16 per-etype mean of edge feats
__device__ __half g_Wh [(size_t)NET * D * KW];        // fp16 weights, TRANSPOSED [et][n][k]
__device__ float  g_mask[(size_t)NET * MAXN];
__device__ int    g_deg[(size_t)NET * MAXN];          // zeroed by gemm epilogue
__device__ int    g_off[(size_t)NET * MAXN];
__device__ int    g_cur[(size_t)NET * MAXN];
__device__ int2   g_csr[(size_t)CAP_TOTAL];           // (src, edge_id)
__device__ int    g_total;                            // zeroed by gemm epilogue

struct EdgeMeta {
    const int*   src[NET];
    const int*   dst[NET];
    const float* ef[NET];
    int          E[NET];
};
struct WPtrs { const float* W[NET]; };

// ---------------------------------------------------------------------------
// 1) fused: x->fp16 | W->fp16^T | edge count
// ---------------------------------------------------------------------------
__global__ void count_prep_kernel(const float* __restrict__ x, WPtrs wp,
                                  EdgeMeta em, int n, int nx, int nw)
{
    int i = blockIdx.x * blockDim.x + threadIdx.x;

    if (i < nx) {
        float4 v0 = __ldg(reinterpret_cast<const float4*>(x) + 2 * i);
        float4 v1 = __ldg(reinterpret_cast<const float4*>(x) + 2 * i + 1);
        __half2 h[4];
        h[0] = __floats2half2_rn(v0.x, v0.y);
        h[1] = __floats2half2_rn(v0.z, v0.w);
        h[2] = __floats2half2_rn(v1.x, v1.y);
        h[3] = __floats2half2_rn(v1.z, v1.w);
        reinterpret_cast<uint4*>(g_xh)[i] = *reinterpret_cast<uint4*>(h);
        return;
    }
    i -= nx;
    if (i < nw) {
        int et = i / (D * KW);
        int r  = i % (D * KW);
        int nn = r / KW;
        int k  = r % KW;
        const float* W = (et == 0) ? wp.W[0] : (et == 1) ? wp.W[1]
                       : (et == 2) ? wp.W[2] : (et == 3) ? wp.W[3] : wp.W[4];
        g_Wh[i] = __float2half_rn(__ldg(&W[k * D + nn]));
        return;
    }
    i -= nw;
    const int* dstp;
    int base;
    if (i < em.E[0]) { dstp = em.dst[0]; base = 0; }
    else {
        i -= em.E[0];
        if (i < em.E[1]) { dstp = em.dst[1]; base = n; }
        else {
            i -= em.E[1];
            if (i < em.E[2]) { dstp = em.dst[2]; base = 2 * n; }
            else {
                i -= em.E[2];
                if (i < em.E[3]) { dstp = em.dst[3]; base = 3 * n; }
                else {
                    i -= em.E[3];
                    if (i >= em.E[4]) return;
                    dstp = em.dst[4]; base = 4 * n;
                }
            }
        }
    }
    atomicAdd(&g_deg[base + __ldg(&dstp[i])], 1);
}

// ---------------------------------------------------------------------------
// 2) alloc: segment offsets via block scan + one global atomic
// ---------------------------------------------------------------------------
__global__ void alloc_kernel(int nelem)
{
    __shared__ int wsum[8];
    int tid  = threadIdx.x;
    int i    = blockIdx.x * 256 + tid;
    int lane = tid & 31;
    int w    = tid >> 5;

    int d = (i < nelem) ? g_deg[i] : 0;
    int v = d;
#pragma unroll
    for (int o = 1; o < 32; o <<= 1) {
        int t = __shfl_up_sync(0xffffffffu, v, o);
        if (lane >= o) v += t;
    }
    if (lane == 31) wsum[w] = v;
    __syncthreads();
    if (tid == 0) {
        int s = 0;
#pragma unroll
        for (int j = 0; j < 8; j++) { int t = wsum[j]; wsum[j] = s; s += t; }
        int b = atomicAdd(&g_total, s);
#pragma unroll
        for (int j = 0; j < 8; j++) wsum[j] += b;
    }
    __syncthreads();
    int off = wsum[w] + v - d;
    if (i < nelem) { g_off[i] = off; g_cur[i] = off; }
}

// ---------------------------------------------------------------------------
// 3) fill CSR: (src, edge_id), one int2 store per edge
// ---------------------------------------------------------------------------
__global__ void fill_kernel(EdgeMeta em, int n)
{
    int et = blockIdx.y;
    int i  = blockIdx.x * blockDim.x + threadIdx.x;
    const int* dst = (et == 0) ? em.dst[0] : (et == 1) ? em.dst[1] : (et == 2) ? em.dst[2]
                   : (et == 3) ? em.dst[3] : em.dst[4];
    const int* src = (et == 0) ? em.src[0] : (et == 1) ? em.src[1] : (et == 2) ? em.src[2]
                   : (et == 3) ? em.src[3] : em.src[4];
    if (i < em.E[et]) {
        int d = __ldg(&dst[i]);
        int s = __ldg(&src[i]);
        int pos = atomicAdd(&g_cur[et * n + d], 1);
        g_csr[pos] = make_int2(s, i);
    }
}

// ---------------------------------------------------------------------------
// 4) combined aggregate: even blocks do x-gather (issue-bound),
//    odd blocks do ef-mean (DRAM-bound). Interleaving mixes both workload
//    types on every SM so the pipes overlap.
// ---------------------------------------------------------------------------
__global__ void __launch_bounds__(256, 6)
aggregate_kernel(EdgeMeta em, int n)
{
    int lane = threadIdx.x & 31;
    int wib  = threadIdx.x >> 5;                 // warp in block
    int role = blockIdx.x & 1;                   // 0 = gather, 1 = efmean
    int gw   = (blockIdx.x >> 1) * 8 + wib;      // (etype,node) id
    if (gw >= NET * n) return;

    int beg = g_off[gw];
    int cnt = g_deg[gw];
    int end = beg + cnt;
    float inv = (cnt > 0) ? (1.0f / (float)cnt) : 0.0f;

    if (role == 0) {
        // ---- x-gather: 2 edges/iter, 16 lanes/edge ----
        int half = lane >> 4;
        int ql   = lane & 15;

        float a[8];
#pragma unroll
        for (int k = 0; k < 8; k++) a[k] = 0.f;

        for (int base = beg; base < end; base += 32) {
            int take = min(32, end - base);
            int mm = 0;
            if (lane < take) mm = __ldg(&g_csr[base + lane]).x;
#pragma unroll
            for (int j = 0; j < 16; j++) {
                if (2 * j >= take) break;
                int e    = 2 * j + half;
                int sidx = __shfl_sync(0xffffffffu, mm, e);
                if (e < take) {
                    uint4 hv = __ldg(reinterpret_cast<const uint4*>(
                                   g_xh + (size_t)sidx * D) + ql);
                    __half2* hp = reinterpret_cast<__half2*>(&hv);
#pragma unroll
                    for (int c = 0; c < 4; c++) {
                        float2 f = __half22float2(hp[c]);
                        a[2 * c]     += f.x;
                        a[2 * c + 1] += f.y;
                    }
                }
            }
        }

#pragma unroll
        for (int k = 0; k < 8; k++) a[k] += __shfl_xor_sync(0xffffffffu, a[k], 16);

        if (half == 0) {
            __half2 o[4];
#pragma unroll
            for (int k = 0; k < 4; k++)
                o[k] = __floats2half2_rn(a[2 * k] * inv, a[2 * k + 1] * inv);
            reinterpret_cast<uint4*>(g_S1h + (size_t)gw * D)[ql] =
                *reinterpret_cast<uint4*>(o);
            if (ql == 0) g_mask[gw] = (cnt > 0) ? 1.0f : 0.0f;
        }
    } else {
        // ---- ef-mean: feature-per-lane, one coalesced 128B load per edge ----
        int et = gw / n;
        const float* __restrict__ ef =
            (et == 0) ? em.ef[0] : (et == 1) ? em.ef[1] : (et == 2) ? em.ef[2]
                      : (et == 3) ? em.ef[3] : em.ef[4];

        float acc = 0.f;

        for (int base = beg; base < end; base += 32) {
            int take = min(32, end - base);
            int2 mm = make_int2(0, 0);
            if (lane < take) mm = __ldg(&g_csr[base + lane]);
#pragma unroll
            for (int j = 0; j < 32; j += 4) {
                if (j >= take) break;
                int e0 = __shfl_sync(0xffffffffu, mm.y, j + 0);
                int e1 = __shfl_sync(0xffffffffu, mm.y, j + 1);
                int e2 = __shfl_sync(0xffffffffu, mm.y, j + 2);
                int e3 = __shfl_sync(0xffffffffu, mm.y, j + 3);
                float v0 = 0.f, v1 = 0.f, v2 = 0.f, v3 = 0.f;
                v0 = __ldg(ef + (size_t)e0 * DE + lane);
                if (j + 1 < take) v1 = __ldg(ef + (size_t)e1 * DE + lane);
                if (j + 2 < take) v2 = __ldg(ef + (size_t)e2 * DE + lane);
                if (j + 3 < take) v3 = __ldg(ef + (size_t)e3 * DE + lane);
                acc += (v0 + v1) + (v2 + v3);
            }
        }

        float m  = acc * inv;
        float hi = __shfl_down_sync(0xffffffffu, m, 1);
        if ((lane & 1) == 0) {
            __half2 h = __floats2half2_rn(m, hi);
            reinterpret_cast<__half2*>(g_S2h + (size_t)gw * DE)[lane >> 1] = h;
        }
    }
}

// ---------------------------------------------------------------------------
// 5) fused GEMM (fp16 HMMA, fp32 accum) + epilogue + state reset
// ---------------------------------------------------------------------------
#define BM  128
#define SAH 168

__device__ __forceinline__ void mma_f16(float* c, const unsigned* a, const unsigned* b)
{
    asm volatile(
        "mma.sync.aligned.m16n8k16.row.col.f32.f16.f16.f32 "
        "{%0,%1,%2,%3}, {%4,%5,%6,%7}, {%8,%9}, {%0,%1,%2,%3};"
        : "+f"(c[0]), "+f"(c[1]), "+f"(c[2]), "+f"(c[3])
        : "r"(a[0]), "r"(a[1]), "r"(a[2]), "r"(a[3]),
          "r"(b[0]), "r"(b[1]));
}

__global__ void __launch_bounds__(256, 2)
gemm_epi_kernel(const float* __restrict__ x,
                const float* __restrict__ b0, const float* __restrict__ b1,
                const float* __restrict__ b2, const float* __restrict__ b3,
                const float* __restrict__ b4,
                float* __restrict__ out, int n)
{
    extern __shared__ __half sm[];
    __half* As = sm;                    // [BM][SAH]
    __half* Bs = sm + (size_t)BM * SAH; // [D][SAH]

    __shared__ float msk[NET][BM];
    __shared__ float bsm[NET][D];

    const float* bp[NET] = {b0, b1, b2, b3, b4};

    int tid  = threadIdx.x;
    int lane = tid & 31;
    int warp = tid >> 5;
    int wm   = (warp & 1) * 64;
    int wn   = (warp >> 1) * 32;
    int lrow = lane >> 2;
    int lcol = lane & 3;
    int row0 = blockIdx.x * BM;

#pragma unroll
    for (int et = 0; et < NET; et++) {
        if (tid < BM) {
            int row = row0 + tid;
            msk[et][tid] = (row < n) ? g_mask[(size_t)et * n + row] : 0.f;
        }
        if (tid < D) bsm[et][tid] = bp[et][tid];
    }

    float c[4][4][4];
#pragma unroll
    for (int s = 0; s < 4; s++)
#pragma unroll
        for (int t = 0; t < 4; t++)
#pragma unroll
            for (int r = 0; r < 4; r++) c[s][t][r] = 0.f;

    __syncthreads();

#pragma unroll 1
    for (int et = 0; et < NET; et++) {
        const __half* __restrict__ S1e = g_S1h + (size_t)et * n * D;
        const __half* __restrict__ S2e = g_S2h + (size_t)et * n * DE;
        const __half* __restrict__ Whe = g_Wh  + (size_t)et * D * KW;

#pragma unroll
        for (int t = 0; t < 10; t++) {
            int idx = tid + t * 256;
            int row = idx / 20;
            int cc  = idx % 20;
            int grow = row0 + row;
            uint4 v = make_uint4(0u, 0u, 0u, 0u);
            if (grow < n) {
                v = (cc < 16)
                  ? __ldg(reinterpret_cast<const uint4*>(S1e + (size_t)grow * D)  + cc)
                  : __ldg(reinterpret_cast<const uint4*>(S2e + (size_t)grow * DE) + (cc - 16));
            }
            *reinterpret_cast<uint4*>(As + (size_t)row * SAH + cc * 8) = v;
        }
#pragma unroll
        for (int t = 0; t < 10; t++) {
            int idx = tid + t * 256;
            int row = idx / 20;
            int cc  = idx % 20;
            uint4 v = __ldg(reinterpret_cast<const uint4*>(Whe + (size_t)row * KW) + cc);
            *reinterpret_cast<uint4*>(Bs + (size_t)row * SAH + cc * 8) = v;
        }
        __syncthreads();

#pragma unroll
        for (int kk = 0; kk < 10; kk++) {
            int k0 = kk * 16;
            unsigned a[4][4], b[4][2];
#pragma unroll
            for (int s = 0; s < 4; s++) {
                int m = wm + s * 16 + lrow;
                const __half* p0 = As + (size_t)m * SAH + k0 + 2 * lcol;
                a[s][0] = *reinterpret_cast<const unsigned*>(p0);
                a[s][1] = *reinterpret_cast<const unsigned*>(p0 + 8 * SAH);
                a[s][2] = *reinterpret_cast<const unsigned*>(p0 + 8);
                a[s][3] = *reinterpret_cast<const unsigned*>(p0 + 8 * SAH + 8);
            }
#pragma unroll
            for (int t = 0; t < 4; t++) {
                int nn = wn + t * 8 + lrow;
                const __half* p0 = Bs + (size_t)nn * SAH + k0 + 2 * lcol;
                b[t][0] = *reinterpret_cast<const unsigned*>(p0);
                b[t][1] = *reinterpret_cast<const unsigned*>(p0 + 8);
            }
#pragma unroll
            for (int s = 0; s < 4; s++)
#pragma unroll
                for (int t = 0; t < 4; t++)
                    mma_f16(c[s][t], a[s], b[t]);
        }
        __syncthreads();
    }

    // epilogue
#pragma unroll
    for (int s = 0; s < 4; s++) {
#pragma unroll
        for (int h = 0; h < 2; h++) {
            int mloc = wm + s * 16 + lrow + h * 8;
            int grow = row0 + mloc;
            if (grow >= n) continue;
            float mk[NET];
#pragma unroll
            for (int et = 0; et < NET; et++) mk[et] = msk[et][mloc];
#pragma unroll
            for (int t = 0; t < 4; t++) {
                int ncol = wn + t * 8 + lcol * 2;
                float bs0 = 0.f, bs1 = 0.f;
#pragma unroll
                for (int et = 0; et < NET; et++) {
                    if (mk[et] > 0.f) {
                        bs0 += bsm[et][ncol];
                        bs1 += bsm[et][ncol + 1];
                    }
                }
                float c0 = c[s][t][h * 2 + 0];
                float c1 = c[s][t][h * 2 + 1];
                const float* xp = x + (size_t)grow * D + ncol;
                float2 o;
                o.x = fmaxf(xp[0] + (c0 + bs0) * 0.2f, 0.f);
                o.y = fmaxf(xp[1] + (c1 + bs1) * 0.2f, 0.f);
                *reinterpret_cast<float2*>(out + (size_t)grow * D + ncol) = o;
            }
        }
    }

    // state reset for next replay: zero degrees + allocator
    int zi = blockIdx.x * blockDim.x + threadIdx.x;
    int zs = gridDim.x * blockDim.x;
    for (int z = zi; z < NET * n; z += zs) g_deg[z] = 0;
    if (zi == 0) g_total = 0;
}

// ---------------------------------------------------------------------------
extern "C" void kernel_launch(void* const* d_in, const int* in_sizes, int n_in,
                              void* d_out, int out_size)
{
    const float* x = (const float*)d_in[0];
    int n = in_sizes[0] / D;
    if (n > MAXN) return;

    EdgeMeta em;
    WPtrs wp;
    const float* b[NET];
    int maxE = 0, totE = 0;
    for (int et = 0; et < NET; et++) {
        em.ef[et]  = (const float*)d_in[1 + 5 * et + 0];
        wp.W[et]   = (const float*)d_in[1 + 5 * et + 1];
        b[et]      = (const float*)d_in[1 + 5 * et + 2];
        em.src[et] = (const int*)  d_in[1 + 5 * et + 3];
        em.dst[et] = (const int*)  d_in[1 + 5 * et + 4];
        em.E[et]   = in_sizes[1 + 5 * et + 3];
        if (em.E[et] > maxE) maxE = em.E[et];
        totE += em.E[et];
    }
    if (totE > CAP_TOTAL) return;
    float* out = (float*)d_out;

    int nelem = NET * n;

    static int smem_bytes = 2 * BM * SAH * (int)sizeof(__half);
    cudaFuncSetAttribute(gemm_epi_kernel,
                         cudaFuncAttributeMaxDynamicSharedMemorySize, smem_bytes);

    // 1) fused prep + count
    {
        int nx = n * D / 8;
        int nw = NET * D * KW;
        int work = nx + nw + totE;
        count_prep_kernel<<<(work + 255) / 256, 256>>>(x, wp, em, n, nx, nw);
    }
    // 2) alloc
    alloc_kernel<<<(nelem + 255) / 256, 256>>>(nelem);
    // 3) fill
    {
        dim3 grid((maxE + 255) / 256, NET);
        fill_kernel<<<grid, 256>>>(em, n);
    }
    // 4) combined gather + ef-mean, block-parity interleaved (profiled launch)
    {
        int nblk = (nelem + 7) / 8;        // 8 warps per block
        aggregate_kernel<<<2 * nblk, 256>>>(em, n);
    }
    // 5) fused GEMM + epilogue + reset
    {
        int blocks = (n + BM - 1) / BM;
        gemm_epi_kernel<<<blocks, 256, smem_bytes>>>(
            x, b[0], b[1], b[2], b[3], b[4], out, n);
    }
}

// round 11
// speedup vs baseline: 1.0530x; 1.0530x over previous
#include <cuda_runtime.h>
#include <cuda_fp16.h>
#include <cstdint>

#define D    128
#define DE   32
#define NET  5
#define MAXN 50000
#define CAP_TOTAL 4000000
#define KW   (D + DE)       // 160

// ---- scratch (device globals: allocation-free; bss zero-init at load) ----
__device__ __half g_xh [(size_t)MAXN * D];            // fp16 op_feats
__device__ __half g_S1h[(size_t)NET * MAXN * D];      // fp16 per-etype mean of src feats
__device__ __half g_S2h[(size_t)NET * MAXN * DE];     // fp16 per-etype mean of edge feats
__device__ __half g_Wh [(size_t)NET * D * KW];        // fp16 weights, TRANSPOSED [et][n][k]
__device__ float  g_mask[(size_t)NET * MAXN];
__device__ int    g_deg[(size_t)NET * MAXN];          // zeroed by gemm epilogue
__device__ int    g_off[(size_t)NET * MAXN];
__device__ int    g_cur[(size_t)NET * MAXN];
__device__ int    g_csr_src[(size_t)CAP_TOTAL];       // src node per CSR slot
__device__ int    g_csr_eid[(size_t)CAP_TOTAL];       // edge id per CSR slot
__device__ int    g_total;                            // zeroed by gemm epilogue

struct EdgeMeta {
    const int*   src[NET];
    const int*   dst[NET];
    const float* ef[NET];
    int          E[NET];
};
struct WPtrs { const float* W[NET]; };

// ---------------------------------------------------------------------------
// 1) fused: x->fp16 | W->fp16^T | edge count
// ---------------------------------------------------------------------------
__global__ void count_prep_kernel(const float* __restrict__ x, WPtrs wp,
                                  EdgeMeta em, int n, int nx, int nw)
{
    int i = blockIdx.x * blockDim.x + threadIdx.x;

    if (i < nx) {
        float4 v0 = __ldg(reinterpret_cast<const float4*>(x) + 2 * i);
        float4 v1 = __ldg(reinterpret_cast<const float4*>(x) + 2 * i + 1);
        __half2 h[4];
        h[0] = __floats2half2_rn(v0.x, v0.y);
        h[1] = __floats2half2_rn(v0.z, v0.w);
        h[2] = __floats2half2_rn(v1.x, v1.y);
        h[3] = __floats2half2_rn(v1.z, v1.w);
        reinterpret_cast<uint4*>(g_xh)[i] = *reinterpret_cast<uint4*>(h);
        return;
    }
    i -= nx;
    if (i < nw) {
        int et = i / (D * KW);
        int r  = i % (D * KW);
        int nn = r / KW;
        int k  = r % KW;
        const float* W = (et == 0) ? wp.W[0] : (et == 1) ? wp.W[1]
                       : (et == 2) ? wp.W[2] : (et == 3) ? wp.W[3] : wp.W[4];
        g_Wh[i] = __float2half_rn(__ldg(&W[k * D + nn]));
        return;
    }
    i -= nw;
    const int* dstp;
    int base;
    if (i < em.E[0]) { dstp = em.dst[0]; base = 0; }
    else {
        i -= em.E[0];
        if (i < em.E[1]) { dstp = em.dst[1]; base = n; }
        else {
            i -= em.E[1];
            if (i < em.E[2]) { dstp = em.dst[2]; base = 2 * n; }
            else {
                i -= em.E[2];
                if (i < em.E[3]) { dstp = em.dst[3]; base = 3 * n; }
                else {
                    i -= em.E[3];
                    if (i >= em.E[4]) return;
                    dstp = em.dst[4]; base = 4 * n;
                }
            }
        }
    }
    atomicAdd(&g_deg[base + __ldg(&dstp[i])], 1);
}

// ---------------------------------------------------------------------------
// 2) alloc: segment offsets via block scan + one global atomic
// ---------------------------------------------------------------------------
__global__ void alloc_kernel(int nelem)
{
    __shared__ int wsum[8];
    int tid  = threadIdx.x;
    int i    = blockIdx.x * 256 + tid;
    int lane = tid & 31;
    int w    = tid >> 5;

    int d = (i < nelem) ? g_deg[i] : 0;
    int v = d;
#pragma unroll
    for (int o = 1; o < 32; o <<= 1) {
        int t = __shfl_up_sync(0xffffffffu, v, o);
        if (lane >= o) v += t;
    }
    if (lane == 31) wsum[w] = v;
    __syncthreads();
    if (tid == 0) {
        int s = 0;
#pragma unroll
        for (int j = 0; j < 8; j++) { int t = wsum[j]; wsum[j] = s; s += t; }
        int b = atomicAdd(&g_total, s);
#pragma unroll
        for (int j = 0; j < 8; j++) wsum[j] += b;
    }
    __syncthreads();
    int off = wsum[w] + v - d;
    if (i < nelem) { g_off[i] = off; g_cur[i] = off; }
}

// ---------------------------------------------------------------------------
// 3) fill CSR: src and edge_id into separate arrays
// ---------------------------------------------------------------------------
__global__ void fill_kernel(EdgeMeta em, int n)
{
    int et = blockIdx.y;
    int i  = blockIdx.x * blockDim.x + threadIdx.x;
    const int* dst = (et == 0) ? em.dst[0] : (et == 1) ? em.dst[1] : (et == 2) ? em.dst[2]
                   : (et == 3) ? em.dst[3] : em.dst[4];
    const int* src = (et == 0) ? em.src[0] : (et == 1) ? em.src[1] : (et == 2) ? em.src[2]
                   : (et == 3) ? em.src[3] : em.src[4];
    if (i < em.E[et]) {
        int d = __ldg(&dst[i]);
        int s = __ldg(&src[i]);
        int pos = atomicAdd(&g_cur[et * n + d], 1);
        g_csr_src[pos] = s;
        g_csr_eid[pos] = i;
    }
}

// ---------------------------------------------------------------------------
// 4) combined aggregate: even blocks x-gather (HADD2 fp16 accumulation),
//    odd blocks ef-mean (feature-per-lane, unroll 8).
// ---------------------------------------------------------------------------
__global__ void __launch_bounds__(256, 6)
aggregate_kernel(EdgeMeta em, int n)
{
    int lane = threadIdx.x & 31;
    int wib  = threadIdx.x >> 5;
    int role = blockIdx.x & 1;
    int gw   = (blockIdx.x >> 1) * 8 + wib;
    if (gw >= NET * n) return;

    int beg = g_off[gw];
    int cnt = g_deg[gw];
    int end = beg + cnt;
    float inv = (cnt > 0) ? (1.0f / (float)cnt) : 0.0f;

    if (role == 0) {
        // ---- x-gather: 2 edges/iter, 16 lanes/edge, fp16 HADD2 accum ----
        int half = lane >> 4;
        int ql   = lane & 15;

        __half2 acc[4];
        __half2 hz = __floats2half2_rn(0.f, 0.f);
#pragma unroll
        for (int k = 0; k < 4; k++) acc[k] = hz;

        for (int base = beg; base < end; base += 32) {
            int take = min(32, end - base);
            int mm = 0;
            if (lane < take) mm = __ldg(&g_csr_src[base + lane]);
#pragma unroll
            for (int j = 0; j < 16; j++) {
                if (2 * j >= take) break;
                int e    = 2 * j + half;
                int sidx = __shfl_sync(0xffffffffu, mm, e);
                if (e < take) {
                    uint4 hv = __ldg(reinterpret_cast<const uint4*>(
                                   g_xh + (size_t)sidx * D) + ql);
                    __half2* hp = reinterpret_cast<__half2*>(&hv);
                    acc[0] = __hadd2(acc[0], hp[0]);
                    acc[1] = __hadd2(acc[1], hp[1]);
                    acc[2] = __hadd2(acc[2], hp[2]);
                    acc[3] = __hadd2(acc[3], hp[3]);
                }
            }
        }

        // combine the two half-warps
#pragma unroll
        for (int k = 0; k < 4; k++) {
            unsigned u = __shfl_xor_sync(0xffffffffu,
                             *reinterpret_cast<unsigned*>(&acc[k]), 16);
            acc[k] = __hadd2(acc[k], *reinterpret_cast<__half2*>(&u));
        }

        if (half == 0) {
            __half2 o[4];
#pragma unroll
            for (int k = 0; k < 4; k++) {
                float2 f = __half22float2(acc[k]);
                o[k] = __floats2half2_rn(f.x * inv, f.y * inv);
            }
            reinterpret_cast<uint4*>(g_S1h + (size_t)gw * D)[ql] =
                *reinterpret_cast<uint4*>(o);
            if (ql == 0) g_mask[gw] = (cnt > 0) ? 1.0f : 0.0f;
        }
    } else {
        // ---- ef-mean: feature-per-lane, 8 edges outstanding ----
        int et = gw / n;
        const float* __restrict__ ef =
            (et == 0) ? em.ef[0] : (et == 1) ? em.ef[1] : (et == 2) ? em.ef[2]
                      : (et == 3) ? em.ef[3] : em.ef[4];

        float acc = 0.f;

        for (int base = beg; base < end; base += 32) {
            int take = min(32, end - base);
            int mm = 0;
            if (lane < take) mm = __ldg(&g_csr_eid[base + lane]);
#pragma unroll
            for (int j = 0; j < 32; j += 8) {
                if (j >= take) break;
                float v[8];
#pragma unroll
                for (int u = 0; u < 8; u++) v[u] = 0.f;
#pragma unroll
                for (int u = 0; u < 8; u++) {
                    int e = __shfl_sync(0xffffffffu, mm, j + u);
                    if (j + u < take)
                        v[u] = __ldg(ef + (size_t)e * DE + lane);
                }
                acc += ((v[0] + v[1]) + (v[2] + v[3]))
                     + ((v[4] + v[5]) + (v[6] + v[7]));
            }
        }

        float m  = acc * inv;
        float hi = __shfl_down_sync(0xffffffffu, m, 1);
        if ((lane & 1) == 0) {
            __half2 h = __floats2half2_rn(m, hi);
            reinterpret_cast<__half2*>(g_S2h + (size_t)gw * DE)[lane >> 1] = h;
        }
    }
}

// ---------------------------------------------------------------------------
// 5) fused GEMM (fp16 HMMA, fp32 accum) + epilogue + state reset
//    BM=64 for better wave balance (782 blocks, 3 CTA/SM).
// ---------------------------------------------------------------------------
#define BM  64
#define SAH 168

__device__ __forceinline__ void mma_f16(float* c, const unsigned* a, const unsigned* b)
{
    asm volatile(
        "mma.sync.aligned.m16n8k16.row.col.f32.f16.f16.f32 "
        "{%0,%1,%2,%3}, {%4,%5,%6,%7}, {%8,%9}, {%0,%1,%2,%3};"
        : "+f"(c[0]), "+f"(c[1]), "+f"(c[2]), "+f"(c[3])
        : "r"(a[0]), "r"(a[1]), "r"(a[2]), "r"(a[3]),
          "r"(b[0]), "r"(b[1]));
}

__global__ void __launch_bounds__(256, 3)
gemm_epi_kernel(const float* __restrict__ x,
                const float* __restrict__ b0, const float* __restrict__ b1,
                const float* __restrict__ b2, const float* __restrict__ b3,
                const float* __restrict__ b4,
                float* __restrict__ out, int n)
{
    extern __shared__ __half sm[];
    __half* As = sm;                    // [BM][SAH]
    __half* Bs = sm + (size_t)BM * SAH; // [D][SAH]

    __shared__ float msk[NET][BM];
    __shared__ float bsm[NET][D];

    const float* bp[NET] = {b0, b1, b2, b3, b4};

    int tid  = threadIdx.x;
    int lane = tid & 31;
    int warp = tid >> 5;
    int wm   = (warp & 1) * 32;          // warp M origin (2 warps over 64)
    int wn   = (warp >> 1) * 32;         // warp N origin (4 warps over 128)
    int lrow = lane >> 2;
    int lcol = lane & 3;
    int row0 = blockIdx.x * BM;

#pragma unroll
    for (int et = 0; et < NET; et++) {
        if (tid < BM) {
            int row = row0 + tid;
            msk[et][tid] = (row < n) ? g_mask[(size_t)et * n + row] : 0.f;
        }
        if (tid < D) bsm[et][tid] = bp[et][tid];
    }

    float c[2][4][4];
#pragma unroll
    for (int s = 0; s < 2; s++)
#pragma unroll
        for (int t = 0; t < 4; t++)
#pragma unroll
            for (int r = 0; r < 4; r++) c[s][t][r] = 0.f;

    __syncthreads();

#pragma unroll 1
    for (int et = 0; et < NET; et++) {
        const __half* __restrict__ S1e = g_S1h + (size_t)et * n * D;
        const __half* __restrict__ S2e = g_S2h + (size_t)et * n * DE;
        const __half* __restrict__ Whe = g_Wh  + (size_t)et * D * KW;

        // A tile: 64 rows x 160 halves = 1280 uint4, 5 iters
#pragma unroll
        for (int t = 0; t < 5; t++) {
            int idx = tid + t * 256;
            int row = idx / 20;
            int cc  = idx % 20;
            int grow = row0 + row;
            uint4 v = make_uint4(0u, 0u, 0u, 0u);
            if (grow < n) {
                v = (cc < 16)
                  ? __ldg(reinterpret_cast<const uint4*>(S1e + (size_t)grow * D)  + cc)
                  : __ldg(reinterpret_cast<const uint4*>(S2e + (size_t)grow * DE) + (cc - 16));
            }
            *reinterpret_cast<uint4*>(As + (size_t)row * SAH + cc * 8) = v;
        }
        // B tile: 128 n-rows x 160 k halves = 2560 uint4, 10 iters
#pragma unroll
        for (int t = 0; t < 10; t++) {
            int idx = tid + t * 256;
            int row = idx / 20;
            int cc  = idx % 20;
            uint4 v = __ldg(reinterpret_cast<const uint4*>(Whe + (size_t)row * KW) + cc);
            *reinterpret_cast<uint4*>(Bs + (size_t)row * SAH + cc * 8) = v;
        }
        __syncthreads();

#pragma unroll
        for (int kk = 0; kk < 10; kk++) {
            int k0 = kk * 16;
            unsigned a[2][4], b[4][2];
#pragma unroll
            for (int s = 0; s < 2; s++) {
                int m = wm + s * 16 + lrow;
                const __half* p0 = As + (size_t)m * SAH + k0 + 2 * lcol;
                a[s][0] = *reinterpret_cast<const unsigned*>(p0);
                a[s][1] = *reinterpret_cast<const unsigned*>(p0 + 8 * SAH);
                a[s][2] = *reinterpret_cast<const unsigned*>(p0 + 8);
                a[s][3] = *reinterpret_cast<const unsigned*>(p0 + 8 * SAH + 8);
            }
#pragma unroll
            for (int t = 0; t < 4; t++) {
                int nn = wn + t * 8 + lrow;
                const __half* p0 = Bs + (size_t)nn * SAH + k0 + 2 * lcol;
                b[t][0] = *reinterpret_cast<const unsigned*>(p0);
                b[t][1] = *reinterpret_cast<const unsigned*>(p0 + 8);
            }
#pragma unroll
            for (int s = 0; s < 2; s++)
#pragma unroll
                for (int t = 0; t < 4; t++)
                    mma_f16(c[s][t], a[s], b[t]);
        }
        __syncthreads();
    }

    // epilogue
#pragma unroll
    for (int s = 0; s < 2; s++) {
#pragma unroll
        for (int h = 0; h < 2; h++) {
            int mloc = wm + s * 16 + lrow + h * 8;
            int grow = row0 + mloc;
            if (grow >= n) continue;
            float mk[NET];
#pragma unroll
            for (int et = 0; et < NET; et++) mk[et] = msk[et][mloc];
#pragma unroll
            for (int t = 0; t < 4; t++) {
                int ncol = wn + t * 8 + lcol * 2;
                float bs0 = 0.f, bs1 = 0.f;
#pragma unroll
                for (int et = 0; et < NET; et++) {
                    if (mk[et] > 0.f) {
                        bs0 += bsm[et][ncol];
                        bs1 += bsm[et][ncol + 1];
                    }
                }
                float c0 = c[s][t][h * 2 + 0];
                float c1 = c[s][t][h * 2 + 1];
                const float* xp = x + (size_t)grow * D + ncol;
                float2 o;
                o.x = fmaxf(xp[0] + (c0 + bs0) * 0.2f, 0.f);
                o.y = fmaxf(xp[1] + (c1 + bs1) * 0.2f, 0.f);
                *reinterpret_cast<float2*>(out + (size_t)grow * D + ncol) = o;
            }
        }
    }

    // state reset for next replay: zero degrees + allocator
    int zi = blockIdx.x * blockDim.x + threadIdx.x;
    int zs = gridDim.x * blockDim.x;
    for (int z = zi; z < NET * n; z += zs) g_deg[z] = 0;
    if (zi == 0) g_total = 0;
}

// ---------------------------------------------------------------------------
extern "C" void kernel_launch(void* const* d_in, const int* in_sizes, int n_in,
                              void* d_out, int out_size)
{
    const float* x = (const float*)d_in[0];
    int n = in_sizes[0] / D;
    if (n > MAXN) return;

    EdgeMeta em;
    WPtrs wp;
    const float* b[NET];
    int maxE = 0, totE = 0;
    for (int et = 0; et < NET; et++) {
        em.ef[et]  = (const float*)d_in[1 + 5 * et + 0];
        wp.W[et]   = (const float*)d_in[1 + 5 * et + 1];
        b[et]      = (const float*)d_in[1 + 5 * et + 2];
        em.src[et] = (const int*)  d_in[1 + 5 * et + 3];
        em.dst[et] = (const int*)  d_in[1 + 5 * et + 4];
        em.E[et]   = in_sizes[1 + 5 * et + 3];
        if (em.E[et] > maxE) maxE = em.E[et];
        totE += em.E[et];
    }
    if (totE > CAP_TOTAL) return;
    float* out = (float*)d_out;

    int nelem = NET * n;

    static int smem_bytes = (BM + D) * SAH * (int)sizeof(__half);
    cudaFuncSetAttribute(gemm_epi_kernel,
                         cudaFuncAttributeMaxDynamicSharedMemorySize, smem_bytes);

    // 1) fused prep + count
    {
        int nx = n * D / 8;
        int nw = NET * D * KW;
        int work = nx + nw + totE;
        count_prep_kernel<<<(work + 255) / 256, 256>>>(x, wp, em, n, nx, nw);
    }
    // 2) alloc
    alloc_kernel<<<(nelem + 255) / 256, 256>>>(nelem);
    // 3) fill
    {
        dim3 grid((maxE + 255) / 256, NET);
        fill_kernel<<<grid, 256>>>(em, n);
    }
    // 4) combined gather + ef-mean (profiled launch)
    {
        int nblk = (nelem + 7) / 8;
        aggregate_kernel<<<2 * nblk, 256>>>(em, n);
    }
    // 5) fused GEMM + epilogue + reset
    {
        int blocks = (n + BM - 1) / BM;
        gemm_epi_kernel<<<blocks, 256, smem_bytes>>>(
            x, b[0], b[1], b[2], b[3], b[4], out, n);
    }
}

// round 12
// speedup vs baseline: 1.1023x; 1.0467x over previous
#include <cuda_runtime.h>
#include <cuda_fp16.h>
#include <cstdint>

#define D    128
#define DE   32
#define NET  5
#define MAXN 50000
#define CAP_TOTAL 4000000
#define KW   (D + DE)       // 160
#define G    32             // nodes per aggregate block
#define CHUNK 2048          // smem CSR staging entries

// ---- scratch (device globals: allocation-free; bss zero-init at load) ----
__device__ __half g_xh [(size_t)MAXN * D];
__device__ __half g_S1h[(size_t)NET * MAXN * D];
__device__ __half g_S2h[(size_t)NET * MAXN * DE];
__device__ __half g_Wh [(size_t)NET * D * KW];        // fp16 weights, TRANSPOSED [et][n][k]
__device__ float  g_mask[(size_t)NET * MAXN];
__device__ int    g_deg[(size_t)NET * MAXN];          // zeroed by gemm epilogue
__device__ int    g_off[(size_t)NET * MAXN];
__device__ int    g_cur[(size_t)NET * MAXN];
__device__ int    g_csr_src[(size_t)CAP_TOTAL];
__device__ int    g_csr_eid[(size_t)CAP_TOTAL];
__device__ int    g_total;                            // zeroed by gemm epilogue

struct EdgeMeta {
    const int*   src[NET];
    const int*   dst[NET];
    const float* ef[NET];
    int          E[NET];
};
struct WPtrs { const float* W[NET]; };

// ---------------------------------------------------------------------------
// 1) fused: x->fp16 | W->fp16^T | edge count
// ---------------------------------------------------------------------------
__global__ void count_prep_kernel(const float* __restrict__ x, WPtrs wp,
                                  EdgeMeta em, int n, int nx, int nw)
{
    int i = blockIdx.x * blockDim.x + threadIdx.x;

    if (i < nx) {
        float4 v0 = __ldg(reinterpret_cast<const float4*>(x) + 2 * i);
        float4 v1 = __ldg(reinterpret_cast<const float4*>(x) + 2 * i + 1);
        __half2 h[4];
        h[0] = __floats2half2_rn(v0.x, v0.y);
        h[1] = __floats2half2_rn(v0.z, v0.w);
        h[2] = __floats2half2_rn(v1.x, v1.y);
        h[3] = __floats2half2_rn(v1.z, v1.w);
        reinterpret_cast<uint4*>(g_xh)[i] = *reinterpret_cast<uint4*>(h);
        return;
    }
    i -= nx;
    if (i < nw) {
        int et = i / (D * KW);
        int r  = i % (D * KW);
        int nn = r / KW;
        int k  = r % KW;
        const float* W = (et == 0) ? wp.W[0] : (et == 1) ? wp.W[1]
                       : (et == 2) ? wp.W[2] : (et == 3) ? wp.W[3] : wp.W[4];
        g_Wh[i] = __float2half_rn(__ldg(&W[k * D + nn]));
        return;
    }
    i -= nw;
    const int* dstp;
    int base;
    if (i < em.E[0]) { dstp = em.dst[0]; base = 0; }
    else {
        i -= em.E[0];
        if (i < em.E[1]) { dstp = em.dst[1]; base = n; }
        else {
            i -= em.E[1];
            if (i < em.E[2]) { dstp = em.dst[2]; base = 2 * n; }
            else {
                i -= em.E[2];
                if (i < em.E[3]) { dstp = em.dst[3]; base = 3 * n; }
                else {
                    i -= em.E[3];
                    if (i >= em.E[4]) return;
                    dstp = em.dst[4]; base = 4 * n;
                }
            }
        }
    }
    atomicAdd(&g_deg[base + __ldg(&dstp[i])], 1);
}

// ---------------------------------------------------------------------------
// 2) alloc: segment offsets via block scan + one global atomic.
//    NOTE: offsets are CONTIGUOUS within each 256-gw scan block (load-bearing
//    for the aggregate kernel's 32-node contiguity assumption; 32 | 256).
// ---------------------------------------------------------------------------
__global__ void alloc_kernel(int nelem)
{
    __shared__ int wsum[8];
    int tid  = threadIdx.x;
    int i    = blockIdx.x * 256 + tid;
    int lane = tid & 31;
    int w    = tid >> 5;

    int d = (i < nelem) ? g_deg[i] : 0;
    int v = d;
#pragma unroll
    for (int o = 1; o < 32; o <<= 1) {
        int t = __shfl_up_sync(0xffffffffu, v, o);
        if (lane >= o) v += t;
    }
    if (lane == 31) wsum[w] = v;
    __syncthreads();
    if (tid == 0) {
        int s = 0;
#pragma unroll
        for (int j = 0; j < 8; j++) { int t = wsum[j]; wsum[j] = s; s += t; }
        int b = atomicAdd(&g_total, s);
#pragma unroll
        for (int j = 0; j < 8; j++) wsum[j] += b;
    }
    __syncthreads();
    int off = wsum[w] + v - d;
    if (i < nelem) { g_off[i] = off; g_cur[i] = off; }
}

// ---------------------------------------------------------------------------
// 3) fill CSR: src and edge_id into separate arrays
// ---------------------------------------------------------------------------
__global__ void fill_kernel(EdgeMeta em, int n)
{
    int et = blockIdx.y;
    int i  = blockIdx.x * blockDim.x + threadIdx.x;
    const int* dst = (et == 0) ? em.dst[0] : (et == 1) ? em.dst[1] : (et == 2) ? em.dst[2]
                   : (et == 3) ? em.dst[3] : em.dst[4];
    const int* src = (et == 0) ? em.src[0] : (et == 1) ? em.src[1] : (et == 2) ? em.src[2]
                   : (et == 3) ? em.src[3] : em.src[4];
    if (i < em.E[et]) {
        int d = __ldg(&dst[i]);
        int s = __ldg(&src[i]);
        int pos = atomicAdd(&g_cur[et * n + d], 1);
        g_csr_src[pos] = s;
        g_csr_eid[pos] = i;
    }
}

// ---------------------------------------------------------------------------
// 4) aggregate: block-cooperative smem staging. Block = 32 consecutive gw,
//    role by block parity (even: x-gather, odd: ef-mean). CSR indices staged
//    through smem; per-node prologue amortized over the whole block.
// ---------------------------------------------------------------------------
__global__ void __launch_bounds__(256, 6)
aggregate_kernel(EdgeMeta em, int n)
{
    __shared__ int s_off[G];
    __shared__ int s_deg[G];
    __shared__ int s_idx[CHUNK];

    int tid  = threadIdx.x;
    int lane = tid & 31;
    int wib  = tid >> 5;
    int role = blockIdx.x & 1;
    int gwb  = (blockIdx.x >> 1) * G;
    int nelem = NET * n;
    int nv   = min(G, nelem - gwb);
    if (nv <= 0) return;   // uniform across block

    if (tid < nv) {
        s_off[tid] = g_off[gwb + tid];
        s_deg[tid] = g_deg[gwb + tid];
    }
    __syncthreads();

    int rbeg = s_off[0];
    int rend = s_off[nv - 1] + s_deg[nv - 1];

    int half = lane >> 4;
    int ql   = lane & 15;

    // per-warp accumulators for its 4 nodes
    __half2 acc[4][4];
    float   facc[4];
    __half2 hz = __floats2half2_rn(0.f, 0.f);
#pragma unroll
    for (int m = 0; m < 4; m++) {
        facc[m] = 0.f;
#pragma unroll
        for (int k = 0; k < 4; k++) acc[m][k] = hz;
    }

    int et = (gwb < nelem) ? (gwb / n) : 0;   // block spans one etype? gwb..gwb+31
    // etype may change mid-block only if n % 32 != 0; handle per-node below.

    for (int cb = rbeg; cb < rend; cb += CHUNK) {
        int clen = min(CHUNK, rend - cb);
        __syncthreads();
        if (role == 0) {
            for (int t = tid; t < clen; t += 256) s_idx[t] = g_csr_src[cb + t];
        } else {
            for (int t = tid; t < clen; t += 256) s_idx[t] = g_csr_eid[cb + t];
        }
        __syncthreads();

        if (role == 0) {
            // ---- x-gather: 2 edges/iter, 16 lanes/edge, HADD2 accum ----
#pragma unroll
            for (int m = 0; m < 4; m++) {
                int idx = wib * 4 + m;
                if (idx >= nv) break;
                int lo = max(s_off[idx], cb);
                int hi = min(s_off[idx] + s_deg[idx], cb + clen);
#pragma unroll 4
                for (int eb = lo; eb < hi; eb += 2) {
                    int e = eb + half;
                    if (e < hi) {
                        int sidx = s_idx[e - cb];
                        uint4 hv = __ldg(reinterpret_cast<const uint4*>(
                                       g_xh + (size_t)sidx * D) + ql);
                        __half2* hp = reinterpret_cast<__half2*>(&hv);
                        acc[m][0] = __hadd2(acc[m][0], hp[0]);
                        acc[m][1] = __hadd2(acc[m][1], hp[1]);
                        acc[m][2] = __hadd2(acc[m][2], hp[2]);
                        acc[m][3] = __hadd2(acc[m][3], hp[3]);
                    }
                }
            }
        } else {
            // ---- ef-mean: feature-per-lane, coalesced 128B per edge ----
#pragma unroll
            for (int m = 0; m < 4; m++) {
                int idx = wib * 4 + m;
                if (idx >= nv) break;
                int gm = gwb + idx;
                int etm = gm / n;
                const float* __restrict__ ef =
                    (etm == 0) ? em.ef[0] : (etm == 1) ? em.ef[1]
                  : (etm == 2) ? em.ef[2] : (etm == 3) ? em.ef[3] : em.ef[4];
                int lo = max(s_off[idx], cb);
                int hi = min(s_off[idx] + s_deg[idx], cb + clen);
                float a = facc[m];
#pragma unroll 4
                for (int e = lo; e < hi; e++) {
                    int eid = s_idx[e - cb];
                    a += __ldg(ef + (size_t)eid * DE + lane);
                }
                facc[m] = a;
            }
        }
    }

    // ---- write-out ----
    if (role == 0) {
#pragma unroll
        for (int m = 0; m < 4; m++) {
            int idx = wib * 4 + m;
            if (idx >= nv) break;
            int gm  = gwb + idx;
            int cnt = s_deg[idx];
            float inv = (cnt > 0) ? (1.0f / (float)cnt) : 0.0f;
            __half2 o[4];
#pragma unroll
            for (int k = 0; k < 4; k++) {
                unsigned u = __shfl_xor_sync(0xffffffffu,
                                 *reinterpret_cast<unsigned*>(&acc[m][k]), 16);
                __half2 s = __hadd2(acc[m][k], *reinterpret_cast<__half2*>(&u));
                float2 f = __half22float2(s);
                o[k] = __floats2half2_rn(f.x * inv, f.y * inv);
            }
            if (half == 0) {
                reinterpret_cast<uint4*>(g_S1h + (size_t)gm * D)[ql] =
                    *reinterpret_cast<uint4*>(o);
                if (ql == 0) g_mask[gm] = (cnt > 0) ? 1.0f : 0.0f;
            }
        }
    } else {
#pragma unroll
        for (int m = 0; m < 4; m++) {
            int idx = wib * 4 + m;
            if (idx >= nv) break;
            int gm  = gwb + idx;
            int cnt = s_deg[idx];
            float inv = (cnt > 0) ? (1.0f / (float)cnt) : 0.0f;
            float v  = facc[m] * inv;
            float hi = __shfl_down_sync(0xffffffffu, v, 1);
            if ((lane & 1) == 0) {
                __half2 h = __floats2half2_rn(v, hi);
                reinterpret_cast<__half2*>(g_S2h + (size_t)gm * DE)[lane >> 1] = h;
            }
        }
    }
    (void)et;
}

// ---------------------------------------------------------------------------
// 5) fused GEMM (fp16 HMMA, fp32 accum) + epilogue + state reset (BM=64)
// ---------------------------------------------------------------------------
#define BM  64
#define SAH 168

__device__ __forceinline__ void mma_f16(float* c, const unsigned* a, const unsigned* b)
{
    asm volatile(
        "mma.sync.aligned.m16n8k16.row.col.f32.f16.f16.f32 "
        "{%0,%1,%2,%3}, {%4,%5,%6,%7}, {%8,%9}, {%0,%1,%2,%3};"
        : "+f"(c[0]), "+f"(c[1]), "+f"(c[2]), "+f"(c[3])
        : "r"(a[0]), "r"(a[1]), "r"(a[2]), "r"(a[3]),
          "r"(b[0]), "r"(b[1]));
}

__global__ void __launch_bounds__(256, 3)
gemm_epi_kernel(const float* __restrict__ x,
                const float* __restrict__ b0, const float* __restrict__ b1,
                const float* __restrict__ b2, const float* __restrict__ b3,
                const float* __restrict__ b4,
                float* __restrict__ out, int n)
{
    extern __shared__ __half sm[];
    __half* As = sm;                    // [BM][SAH]
    __half* Bs = sm + (size_t)BM * SAH; // [D][SAH]

    __shared__ float msk[NET][BM];
    __shared__ float bsm[NET][D];

    const float* bp[NET] = {b0, b1, b2, b3, b4};

    int tid  = threadIdx.x;
    int lane = tid & 31;
    int warp = tid >> 5;
    int wm   = (warp & 1) * 32;
    int wn   = (warp >> 1) * 32;
    int lrow = lane >> 2;
    int lcol = lane & 3;
    int row0 = blockIdx.x * BM;

#pragma unroll
    for (int et = 0; et < NET; et++) {
        if (tid < BM) {
            int row = row0 + tid;
            msk[et][tid] = (row < n) ? g_mask[(size_t)et * n + row] : 0.f;
        }
        if (tid < D) bsm[et][tid] = bp[et][tid];
    }

    float c[2][4][4];
#pragma unroll
    for (int s = 0; s < 2; s++)
#pragma unroll
        for (int t = 0; t < 4; t++)
#pragma unroll
            for (int r = 0; r < 4; r++) c[s][t][r] = 0.f;

    __syncthreads();

#pragma unroll 1
    for (int et = 0; et < NET; et++) {
        const __half* __restrict__ S1e = g_S1h + (size_t)et * n * D;
        const __half* __restrict__ S2e = g_S2h + (size_t)et * n * DE;
        const __half* __restrict__ Whe = g_Wh  + (size_t)et * D * KW;

#pragma unroll
        for (int t = 0; t < 5; t++) {
            int idx = tid + t * 256;
            int row = idx / 20;
            int cc  = idx % 20;
            int grow = row0 + row;
            uint4 v = make_uint4(0u, 0u, 0u, 0u);
            if (grow < n) {
                v = (cc < 16)
                  ? __ldg(reinterpret_cast<const uint4*>(S1e + (size_t)grow * D)  + cc)
                  : __ldg(reinterpret_cast<const uint4*>(S2e + (size_t)grow * DE) + (cc - 16));
            }
            *reinterpret_cast<uint4*>(As + (size_t)row * SAH + cc * 8) = v;
        }
#pragma unroll
        for (int t = 0; t < 10; t++) {
            int idx = tid + t * 256;
            int row = idx / 20;
            int cc  = idx % 20;
            uint4 v = __ldg(reinterpret_cast<const uint4*>(Whe + (size_t)row * KW) + cc);
            *reinterpret_cast<uint4*>(Bs + (size_t)row * SAH + cc * 8) = v;
        }
        __syncthreads();

#pragma unroll
        for (int kk = 0; kk < 10; kk++) {
            int k0 = kk * 16;
            unsigned a[2][4], b[4][2];
#pragma unroll
            for (int s = 0; s < 2; s++) {
                int m = wm + s * 16 + lrow;
                const __half* p0 = As + (size_t)m * SAH + k0 + 2 * lcol;
                a[s][0] = *reinterpret_cast<const unsigned*>(p0);
                a[s][1] = *reinterpret_cast<const unsigned*>(p0 + 8 * SAH);
                a[s][2] = *reinterpret_cast<const unsigned*>(p0 + 8);
                a[s][3] = *reinterpret_cast<const unsigned*>(p0 + 8 * SAH + 8);
            }
#pragma unroll
            for (int t = 0; t < 4; t++) {
                int nn = wn + t * 8 + lrow;
                const __half* p0 = Bs + (size_t)nn * SAH + k0 + 2 * lcol;
                b[t][0] = *reinterpret_cast<const unsigned*>(p0);
                b[t][1] = *reinterpret_cast<const unsigned*>(p0 + 8);
            }
#pragma unroll
            for (int s = 0; s < 2; s++)
#pragma unroll
                for (int t = 0; t < 4; t++)
                    mma_f16(c[s][t], a[s], b[t]);
        }
        __syncthreads();
    }

    // epilogue
#pragma unroll
    for (int s = 0; s < 2; s++) {
#pragma unroll
        for (int h = 0; h < 2; h++) {
            int mloc = wm + s * 16 + lrow + h * 8;
            int grow = row0 + mloc;
            if (grow >= n) continue;
            float mk[NET];
#pragma unroll
            for (int et = 0; et < NET; et++) mk[et] = msk[et][mloc];
#pragma unroll
            for (int t = 0; t < 4; t++) {
                int ncol = wn + t * 8 + lcol * 2;
                float bs0 = 0.f, bs1 = 0.f;
#pragma unroll
                for (int et = 0; et < NET; et++) {
                    if (mk[et] > 0.f) {
                        bs0 += bsm[et][ncol];
                        bs1 += bsm[et][ncol + 1];
                    }
                }
                float c0 = c[s][t][h * 2 + 0];
                float c1 = c[s][t][h * 2 + 1];
                const float* xp = x + (size_t)grow * D + ncol;
                float2 o;
                o.x = fmaxf(xp[0] + (c0 + bs0) * 0.2f, 0.f);
                o.y = fmaxf(xp[1] + (c1 + bs1) * 0.2f, 0.f);
                *reinterpret_cast<float2*>(out + (size_t)grow * D + ncol) = o;
            }
        }
    }

    // state reset for next replay: zero degrees + allocator
    int zi = blockIdx.x * blockDim.x + threadIdx.x;
    int zs = gridDim.x * blockDim.x;
    for (int z = zi; z < NET * n; z += zs) g_deg[z] = 0;
    if (zi == 0) g_total = 0;
}

// ---------------------------------------------------------------------------
extern "C" void kernel_launch(void* const* d_in, const int* in_sizes, int n_in,
                              void* d_out, int out_size)
{
    const float* x = (const float*)d_in[0];
    int n = in_sizes[0] / D;
    if (n > MAXN) return;

    EdgeMeta em;
    WPtrs wp;
    const float* b[NET];
    int maxE = 0, totE = 0;
    for (int et = 0; et < NET; et++) {
        em.ef[et]  = (const float*)d_in[1 + 5 * et + 0];
        wp.W[et]   = (const float*)d_in[1 + 5 * et + 1];
        b[et]      = (const float*)d_in[1 + 5 * et + 2];
        em.src[et] = (const int*)  d_in[1 + 5 * et + 3];
        em.dst[et] = (const int*)  d_in[1 + 5 * et + 4];
        em.E[et]   = in_sizes[1 + 5 * et + 3];
        if (em.E[et] > maxE) maxE = em.E[et];
        totE += em.E[et];
    }
    if (totE > CAP_TOTAL) return;
    float* out = (float*)d_out;

    int nelem = NET * n;

    static int smem_bytes = (BM + D) * SAH * (int)sizeof(__half);
    cudaFuncSetAttribute(gemm_epi_kernel,
                         cudaFuncAttributeMaxDynamicSharedMemorySize, smem_bytes);

    // 1) fused prep + count
    {
        int nx = n * D / 8;
        int nw = NET * D * KW;
        int work = nx + nw + totE;
        count_prep_kernel<<<(work + 255) / 256, 256>>>(x, wp, em, n, nx, nw);
    }
    // 2) alloc
    alloc_kernel<<<(nelem + 255) / 256, 256>>>(nelem);
    // 3) fill
    {
        dim3 grid((maxE + 255) / 256, NET);
        fill_kernel<<<grid, 256>>>(em, n);
    }
    // 4) block-cooperative aggregate (profiled launch)
    {
        int nblk = (nelem + G - 1) / G;
        aggregate_kernel<<<2 * nblk, 256>>>(em, n);
    }
    // 5) fused GEMM + epilogue + reset
    {
        int blocks = (n + BM - 1) / BM;
        gemm_epi_kernel<<<blocks, 256, smem_bytes>>>(
            x, b[0], b[1], b[2], b[3], b[4], out, n);
    }
}

// round 14
// speedup vs baseline: 1.1683x; 1.0599x over previous
#include <cuda_runtime.h>
#include <cuda_fp16.h>
#include <cstdint>

#define D    128
#define DE   32
#define NET  5
#define MAXN 50000
#define CAP_TOTAL 4000000
#define KW   (D + DE)       // 160
#define G    16             // nodes per aggregate block (16 | 256 scan block)
#define CHUNK 1024          // smem CSR staging entries

// ---- scratch (device globals: allocation-free; bss zero-init at load) ----
__device__ __align__(16) __half g_xh [(size_t)MAXN * D];
__device__ __align__(16) __half g_S1h[(size_t)NET * MAXN * D];
__device__ __align__(16) __half g_S2h[(size_t)NET * MAXN * DE];
__device__ __align__(16) __half g_Wh [(size_t)NET * D * KW];     // fp16 weights, TRANSPOSED [et][n][k]
__device__ float  g_mask[(size_t)NET * MAXN];
__device__ int    g_deg[(size_t)NET * MAXN];          // zeroed by gemm epilogue
__device__ int    g_off[(size_t)NET * MAXN];
__device__ int    g_cur[(size_t)NET * MAXN];
__device__ int    g_csr_src[(size_t)CAP_TOTAL];
__device__ int    g_csr_eid[(size_t)CAP_TOTAL];
__device__ int    g_total;                            // zeroed by gemm epilogue

struct EdgeMeta {
    const int*   src[NET];
    const int*   dst[NET];
    const float* ef[NET];
    int          E[NET];
};
struct WPtrs { const float* W[NET]; };

// ---------------------------------------------------------------------------
// 1) fused: x->fp16 | W->fp16^T | edge count
// ---------------------------------------------------------------------------
__global__ void count_prep_kernel(const float* __restrict__ x, WPtrs wp,
                                  EdgeMeta em, int n, int nx, int nw)
{
    int i = blockIdx.x * blockDim.x + threadIdx.x;

    if (i < nx) {
        float4 v0 = __ldg(reinterpret_cast<const float4*>(x) + 2 * i);
        float4 v1 = __ldg(reinterpret_cast<const float4*>(x) + 2 * i + 1);
        __half2 h[4];
        h[0] = __floats2half2_rn(v0.x, v0.y);
        h[1] = __floats2half2_rn(v0.z, v0.w);
        h[2] = __floats2half2_rn(v1.x, v1.y);
        h[3] = __floats2half2_rn(v1.z, v1.w);
        reinterpret_cast<uint4*>(g_xh)[i] = *reinterpret_cast<uint4*>(h);
        return;
    }
    i -= nx;
    if (i < nw) {
        int et = i / (D * KW);
        int r  = i % (D * KW);
        int nn = r / KW;
        int k  = r % KW;
        const float* W = (et == 0) ? wp.W[0] : (et == 1) ? wp.W[1]
                       : (et == 2) ? wp.W[2] : (et == 3) ? wp.W[3] : wp.W[4];
        g_Wh[i] = __float2half_rn(__ldg(&W[k * D + nn]));
        return;
    }
    i -= nw;
    const int* dstp;
    int base;
    if (i < em.E[0]) { dstp = em.dst[0]; base = 0; }
    else {
        i -= em.E[0];
        if (i < em.E[1]) { dstp = em.dst[1]; base = n; }
        else {
            i -= em.E[1];
            if (i < em.E[2]) { dstp = em.dst[2]; base = 2 * n; }
            else {
                i -= em.E[2];
                if (i < em.E[3]) { dstp = em.dst[3]; base = 3 * n; }
                else {
                    i -= em.E[3];
                    if (i >= em.E[4]) return;
                    dstp = em.dst[4]; base = 4 * n;
                }
            }
        }
    }
    atomicAdd(&g_deg[base + __ldg(&dstp[i])], 1);
}

// ---------------------------------------------------------------------------
// 2) alloc: segment offsets via block scan + one global atomic.
//    Offsets CONTIGUOUS within each 256-gw scan block (16 | 256 load-bearing).
// ---------------------------------------------------------------------------
__global__ void alloc_kernel(int nelem)
{
    __shared__ int wsum[8];
    int tid  = threadIdx.x;
    int i    = blockIdx.x * 256 + tid;
    int lane = tid & 31;
    int w    = tid >> 5;

    int d = (i < nelem) ? g_deg[i] : 0;
    int v = d;
#pragma unroll
    for (int o = 1; o < 32; o <<= 1) {
        int t = __shfl_up_sync(0xffffffffu, v, o);
        if (lane >= o) v += t;
    }
    if (lane == 31) wsum[w] = v;
    __syncthreads();
    if (tid == 0) {
        int s = 0;
#pragma unroll
        for (int j = 0; j < 8; j++) { int t = wsum[j]; wsum[j] = s; s += t; }
        int b = atomicAdd(&g_total, s);
#pragma unroll
        for (int j = 0; j < 8; j++) wsum[j] += b;
    }
    __syncthreads();
    int off = wsum[w] + v - d;
    if (i < nelem) { g_off[i] = off; g_cur[i] = off; }
}

// ---------------------------------------------------------------------------
// 3) fill CSR: src and edge_id into separate arrays
// ---------------------------------------------------------------------------
__global__ void fill_kernel(EdgeMeta em, int n)
{
    int et = blockIdx.y;
    int i  = blockIdx.x * blockDim.x + threadIdx.x;
    const int* dst = (et == 0) ? em.dst[0] : (et == 1) ? em.dst[1] : (et == 2) ? em.dst[2]
                   : (et == 3) ? em.dst[3] : em.dst[4];
    const int* src = (et == 0) ? em.src[0] : (et == 1) ? em.src[1] : (et == 2) ? em.src[2]
                   : (et == 3) ? em.src[3] : em.src[4];
    if (i < em.E[et]) {
        int d = __ldg(&dst[i]);
        int s = __ldg(&src[i]);
        int pos = atomicAdd(&g_cur[et * n + d], 1);
        g_csr_src[pos] = s;
        g_csr_eid[pos] = i;
    }
}

// ---------------------------------------------------------------------------
// 4) aggregate: block-cooperative smem staging, 16 nodes/block, 2 nodes/warp
//    (register-slim for 8 blocks/SM = 64 warps). Role by block parity:
//    even blocks x-gather (HADD2), odd blocks ef-mean (fp32 accum).
// ---------------------------------------------------------------------------
__global__ void __launch_bounds__(256, 8)
aggregate_kernel(EdgeMeta em, int n)
{
    __shared__ int s_off[G];
    __shared__ int s_deg[G];
    __shared__ int s_idx[CHUNK];

    int tid  = threadIdx.x;
    int lane = tid & 31;
    int wib  = tid >> 5;
    int role = blockIdx.x & 1;
    int gwb  = (blockIdx.x >> 1) * G;
    int nelem = NET * n;
    int nv   = min(G, nelem - gwb);
    if (nv <= 0) return;

    if (tid < nv) {
        s_off[tid] = g_off[gwb + tid];
        s_deg[tid] = g_deg[gwb + tid];
    }
    __syncthreads();

    int rbeg = s_off[0];
    int rend = s_off[nv - 1] + s_deg[nv - 1];

    int half = lane >> 4;
    int ql   = lane & 15;

    // per-warp accumulators for its 2 nodes
    __half2 acc[2][4];
    float   facc[2];
    __half2 hz = __floats2half2_rn(0.f, 0.f);
#pragma unroll
    for (int m = 0; m < 2; m++) {
        facc[m] = 0.f;
#pragma unroll
        for (int k = 0; k < 4; k++) acc[m][k] = hz;
    }

    for (int cb = rbeg; cb < rend; cb += CHUNK) {
        int clen = min(CHUNK, rend - cb);
        __syncthreads();
        if (role == 0) {
            for (int t = tid; t < clen; t += 256) s_idx[t] = g_csr_src[cb + t];
        } else {
            for (int t = tid; t < clen; t += 256) s_idx[t] = g_csr_eid[cb + t];
        }
        __syncthreads();

        if (role == 0) {
            // ---- x-gather: 2 edges/iter, 16 lanes/edge, HADD2 accum ----
#pragma unroll
            for (int m = 0; m < 2; m++) {
                int idx = wib * 2 + m;
                if (idx >= nv) break;
                int lo = max(s_off[idx], cb);
                int hi = min(s_off[idx] + s_deg[idx], cb + clen);
#pragma unroll 4
                for (int eb = lo; eb < hi; eb += 2) {
                    int e = eb + half;
                    if (e < hi) {
                        int sidx = s_idx[e - cb];
                        uint4 hv = __ldg(reinterpret_cast<const uint4*>(
                                       g_xh + (size_t)sidx * D) + ql);
                        __half2* hp = reinterpret_cast<__half2*>(&hv);
                        acc[m][0] = __hadd2(acc[m][0], hp[0]);
                        acc[m][1] = __hadd2(acc[m][1], hp[1]);
                        acc[m][2] = __hadd2(acc[m][2], hp[2]);
                        acc[m][3] = __hadd2(acc[m][3], hp[3]);
                    }
                }
            }
        } else {
            // ---- ef-mean: feature-per-lane, coalesced 128B per edge ----
#pragma unroll
            for (int m = 0; m < 2; m++) {
                int idx = wib * 2 + m;
                if (idx >= nv) break;
                int gm  = gwb + idx;
                int etm = gm / n;
                const float* __restrict__ ef =
                    (etm == 0) ? em.ef[0] : (etm == 1) ? em.ef[1]
                  : (etm == 2) ? em.ef[2] : (etm == 3) ? em.ef[3] : em.ef[4];
                int lo = max(s_off[idx], cb);
                int hi = min(s_off[idx] + s_deg[idx], cb + clen);
                float a = facc[m];
#pragma unroll 4
                for (int e = lo; e < hi; e++) {
                    int eid = s_idx[e - cb];
                    a += __ldg(ef + (size_t)eid * DE + lane);
                }
                facc[m] = a;
            }
        }
    }

    // ---- write-out ----
    if (role == 0) {
#pragma unroll
        for (int m = 0; m < 2; m++) {
            int idx = wib * 2 + m;
            if (idx >= nv) break;
            int gm  = gwb + idx;
            int cnt = s_deg[idx];
            float inv = (cnt > 0) ? (1.0f / (float)cnt) : 0.0f;
            __half2 o[4];
#pragma unroll
            for (int k = 0; k < 4; k++) {
                unsigned u = __shfl_xor_sync(0xffffffffu,
                                 *reinterpret_cast<unsigned*>(&acc[m][k]), 16);
                __half2 s = __hadd2(acc[m][k], *reinterpret_cast<__half2*>(&u));
                float2 f = __half22float2(s);
                o[k] = __floats2half2_rn(f.x * inv, f.y * inv);
            }
            if (half == 0) {
                reinterpret_cast<uint4*>(g_S1h + (size_t)gm * D)[ql] =
                    *reinterpret_cast<uint4*>(o);
                if (ql == 0) g_mask[gm] = (cnt > 0) ? 1.0f : 0.0f;
            }
        }
    } else {
#pragma unroll
        for (int m = 0; m < 2; m++) {
            int idx = wib * 2 + m;
            if (idx >= nv) break;
            int gm  = gwb + idx;
            int cnt = s_deg[idx];
            float inv = (cnt > 0) ? (1.0f / (float)cnt) : 0.0f;
            float v  = facc[m] * inv;
            float hi = __shfl_down_sync(0xffffffffu, v, 1);
            if ((lane & 1) == 0) {
                __half2 h = __floats2half2_rn(v, hi);
                reinterpret_cast<__half2*>(g_S2h + (size_t)gm * DE)[lane >> 1] = h;
            }
        }
    }
}

// ---------------------------------------------------------------------------
// 5) fused GEMM (fp16 HMMA, fp32 accum) + epilogue + state reset (BM=64)
// ---------------------------------------------------------------------------
#define BM  64
#define SAH 168

__device__ __forceinline__ void mma_f16(float* c, const unsigned* a, const unsigned* b)
{
    asm volatile(
        "mma.sync.aligned.m16n8k16.row.col.f32.f16.f16.f32 "
        "{%0,%1,%2,%3}, {%4,%5,%6,%7}, {%8,%9}, {%0,%1,%2,%3};"
        : "+f"(c[0]), "+f"(c[1]), "+f"(c[2]), "+f"(c[3])
        : "r"(a[0]), "r"(a[1]), "r"(a[2]), "r"(a[3]),
          "r"(b[0]), "r"(b[1]));
}

__global__ void __launch_bounds__(256, 3)
gemm_epi_kernel(const float* __restrict__ x,
                const float* __restrict__ b0, const float* __restrict__ b1,
                const float* __restrict__ b2, const float* __restrict__ b3,
                const float* __restrict__ b4,
                float* __restrict__ out, int n)
{
    extern __shared__ __half sm[];
    __half* As = sm;                    // [BM][SAH]
    __half* Bs = sm + (size_t)BM * SAH; // [D][SAH]

    __shared__ float msk[NET][BM];
    __shared__ float bsm[NET][D];

    const float* bp[NET] = {b0, b1, b2, b3, b4};

    int tid  = threadIdx.x;
    int lane = tid & 31;
    int warp = tid >> 5;
    int wm   = (warp & 1) * 32;
    int wn   = (warp >> 1) * 32;
    int lrow = lane >> 2;
    int lcol = lane & 3;
    int row0 = blockIdx.x * BM;

#pragma unroll
    for (int et = 0; et < NET; et++) {
        if (tid < BM) {
            int row = row0 + tid;
            msk[et][tid] = (row < n) ? g_mask[(size_t)et * n + row] : 0.f;
        }
        if (tid < D) bsm[et][tid] = bp[et][tid];
    }

    float c[2][4][4];
#pragma unroll
    for (int s = 0; s < 2; s++)
#pragma unroll
        for (int t = 0; t < 4; t++)
#pragma unroll
            for (int r = 0; r < 4; r++) c[s][t][r] = 0.f;

    __syncthreads();

#pragma unroll 1
    for (int et = 0; et < NET; et++) {
        const __half* __restrict__ S1e = g_S1h + (size_t)et * n * D;
        const __half* __restrict__ S2e = g_S2h + (size_t)et * n * DE;
        const __half* __restrict__ Whe = g_Wh  + (size_t)et * D * KW;

#pragma unroll
        for (int t = 0; t < 5; t++) {
            int idx = tid + t * 256;
            int row = idx / 20;
            int cc  = idx % 20;
            int grow = row0 + row;
            uint4 v = make_uint4(0u, 0u, 0u, 0u);
            if (grow < n) {
                v = (cc < 16)
                  ? __ldg(reinterpret_cast<const uint4*>(S1e + (size_t)grow * D)  + cc)
                  : __ldg(reinterpret_cast<const uint4*>(S2e + (size_t)grow * DE) + (cc - 16));
            }
            *reinterpret_cast<uint4*>(As + (size_t)row * SAH + cc * 8) = v;
        }
#pragma unroll
        for (int t = 0; t < 10; t++) {
            int idx = tid + t * 256;
            int row = idx / 20;
            int cc  = idx % 20;
            uint4 v = __ldg(reinterpret_cast<const uint4*>(Whe + (size_t)row * KW) + cc);
            *reinterpret_cast<uint4*>(Bs + (size_t)row * SAH + cc * 8) = v;
        }
        __syncthreads();

#pragma unroll
        for (int kk = 0; kk < 10; kk++) {
            int k0 = kk * 16;
            unsigned a[2][4], b[4][2];
#pragma unroll
            for (int s = 0; s < 2; s++) {
                int m = wm + s * 16 + lrow;
                const __half* p0 = As + (size_t)m * SAH + k0 + 2 * lcol;
                a[s][0] = *reinterpret_cast<const unsigned*>(p0);
                a[s][1] = *reinterpret_cast<const unsigned*>(p0 + 8 * SAH);
                a[s][2] = *reinterpret_cast<const unsigned*>(p0 + 8);
                a[s][3] = *reinterpret_cast<const unsigned*>(p0 + 8 * SAH + 8);
            }
#pragma unroll
            for (int t = 0; t < 4; t++) {
                int nn = wn + t * 8 + lrow;
                const __half* p0 = Bs + (size_t)nn * SAH + k0 + 2 * lcol;
                b[t][0] = *reinterpret_cast<const unsigned*>(p0);
                b[t][1] = *reinterpret_cast<const unsigned*>(p0 + 8);
            }
#pragma unroll
            for (int s = 0; s < 2; s++)
#pragma unroll
                for (int t = 0; t < 4; t++)
                    mma_f16(c[s][t], a[s], b[t]);
        }
        __syncthreads();
    }

    // epilogue
#pragma unroll
    for (int s = 0; s < 2; s++) {
#pragma unroll
        for (int h = 0; h < 2; h++) {
            int mloc = wm + s * 16 + lrow + h * 8;
            int grow = row0 + mloc;
            if (grow >= n) continue;
            float mk[NET];
#pragma unroll
            for (int et = 0; et < NET; et++) mk[et] = msk[et][mloc];
#pragma unroll
            for (int t = 0; t < 4; t++) {
                int ncol = wn + t * 8 + lcol * 2;
                float bs0 = 0.f, bs1 = 0.f;
#pragma unroll
                for (int et = 0; et < NET; et++) {
                    if (mk[et] > 0.f) {
                        bs0 += bsm[et][ncol];
                        bs1 += bsm[et][ncol + 1];
                    }
                }
                float c0 = c[s][t][h * 2 + 0];
                float c1 = c[s][t][h * 2 + 1];
                const float* xp = x + (size_t)grow * D + ncol;
                float2 o;
                o.x = fmaxf(xp[0] + (c0 + bs0) * 0.2f, 0.f);
                o.y = fmaxf(xp[1] + (c1 + bs1) * 0.2f, 0.f);
                *reinterpret_cast<float2*>(out + (size_t)grow * D + ncol) = o;
            }
        }
    }

    // state reset for next replay: zero degrees + allocator
    int zi = blockIdx.x * blockDim.x + threadIdx.x;
    int zs = gridDim.x * blockDim.x;
    for (int z = zi; z < NET * n; z += zs) g_deg[z] = 0;
    if (zi == 0) g_total = 0;
}

// ---------------------------------------------------------------------------
extern "C" void kernel_launch(void* const* d_in, const int* in_sizes, int n_in,
                              void* d_out, int out_size)
{
    const float* x = (const float*)d_in[0];
    int n = in_sizes[0] / D;
    if (n > MAXN) return;

    EdgeMeta em;
    WPtrs wp;
    const float* b[NET];
    int maxE = 0, totE = 0;
    for (int et = 0; et < NET; et++) {
        em.ef[et]  = (const float*)d_in[1 + 5 * et + 0];
        wp.W[et]   = (const float*)d_in[1 + 5 * et + 1];
        b[et]      = (const float*)d_in[1 + 5 * et + 2];
        em.src[et] = (const int*)  d_in[1 + 5 * et + 3];
        em.dst[et] = (const int*)  d_in[1 + 5 * et + 4];
        em.E[et]   = in_sizes[1 + 5 * et + 3];
        if (em.E[et] > maxE) maxE = em.E[et];
        totE += em.E[et];
    }
    if (totE > CAP_TOTAL) return;
    float* out = (float*)d_out;

    int nelem = NET * n;

    static int smem_bytes = (BM + D) * SAH * (int)sizeof(__half);
    cudaFuncSetAttribute(gemm_epi_kernel,
                         cudaFuncAttributeMaxDynamicSharedMemorySize, smem_bytes);

    // 1) fused prep + count
    {
        int nx = n * D / 8;
        int nw = NET * D * KW;
        int work = nx + nw + totE;
        count_prep_kernel<<<(work + 255) / 256, 256>>>(x, wp, em, n, nx, nw);
    }
    // 2) alloc
    alloc_kernel<<<(nelem + 255) / 256, 256>>>(nelem);
    // 3) fill
    {
        dim3 grid((maxE + 255) / 256, NET);
        fill_kernel<<<grid, 256>>>(em, n);
    }
    // 4) block-cooperative aggregate, 8 blocks/SM (profiled launch)
    {
        int nblk = (nelem + G - 1) / G;
        aggregate_kernel<<<2 * nblk, 256>>>(em, n);
    }
    // 5) fused GEMM + epilogue + reset
    {
        int blocks = (n + BM - 1) / BM;
        gemm_epi_kernel<<<blocks, 256, smem_bytes>>>(
            x, b[0], b[1], b[2], b[3], b[4], out, n);
    }
}

// round 15
// speedup vs baseline: 1.2426x; 1.0636x over previous
#include <cuda_runtime.h>
#include <cuda_fp16.h>
#include <cstdint>

#define D    128
#define DE   32
#define NET  5
#define MAXN 50000
#define CAP_TOTAL 4000000
#define KW   (D + DE)       // 160
#define G    16             // nodes per aggregate block (16 | 256 scan block)
#define CHUNK 1024          // smem CSR staging entries

// ---- scratch (device globals: allocation-free; bss zero-init at load) ----
__device__ __align__(16) __half g_xh [(size_t)MAXN * D];
__device__ __align__(16) __half g_S1h[(size_t)NET * MAXN * D];
__device__ __align__(16) __half g_S2h[(size_t)NET * MAXN * DE];
__device__ __align__(16) __half g_Wh [(size_t)NET * D * KW];     // fp16 weights, TRANSPOSED [et][n][k]
__device__ float  g_mask[(size_t)NET * MAXN];
__device__ int    g_deg[(size_t)NET * MAXN];          // zeroed by gemm epilogue
__device__ int    g_off[(size_t)NET * MAXN];
__device__ int    g_cur[(size_t)NET * MAXN];
__device__ int    g_csr_src[(size_t)CAP_TOTAL];
__device__ int    g_csr_eid[(size_t)CAP_TOTAL];
__device__ int    g_total;                            // zeroed by gemm epilogue

struct EdgeMeta {
    const int*   src[NET];
    const int*   dst[NET];
    const float* ef[NET];
    int          E[NET];
};
struct WPtrs { const float* W[NET]; };

// ---------------------------------------------------------------------------
// 1) fused: x->fp16 | W->fp16^T | edge count
// ---------------------------------------------------------------------------
__global__ void count_prep_kernel(const float* __restrict__ x, WPtrs wp,
                                  EdgeMeta em, int n, int nx, int nw)
{
    int i = blockIdx.x * blockDim.x + threadIdx.x;

    if (i < nx) {
        float4 v0 = __ldg(reinterpret_cast<const float4*>(x) + 2 * i);
        float4 v1 = __ldg(reinterpret_cast<const float4*>(x) + 2 * i + 1);
        __half2 h[4];
        h[0] = __floats2half2_rn(v0.x, v0.y);
        h[1] = __floats2half2_rn(v0.z, v0.w);
        h[2] = __floats2half2_rn(v1.x, v1.y);
        h[3] = __floats2half2_rn(v1.z, v1.w);
        reinterpret_cast<uint4*>(g_xh)[i] = *reinterpret_cast<uint4*>(h);
        return;
    }
    i -= nx;
    if (i < nw) {
        int et = i / (D * KW);
        int r  = i % (D * KW);
        int nn = r / KW;
        int k  = r % KW;
        const float* W = (et == 0) ? wp.W[0] : (et == 1) ? wp.W[1]
                       : (et == 2) ? wp.W[2] : (et == 3) ? wp.W[3] : wp.W[4];
        g_Wh[i] = __float2half_rn(__ldg(&W[k * D + nn]));
        return;
    }
    i -= nw;
    const int* dstp;
    int base;
    if (i < em.E[0]) { dstp = em.dst[0]; base = 0; }
    else {
        i -= em.E[0];
        if (i < em.E[1]) { dstp = em.dst[1]; base = n; }
        else {
            i -= em.E[1];
            if (i < em.E[2]) { dstp = em.dst[2]; base = 2 * n; }
            else {
                i -= em.E[2];
                if (i < em.E[3]) { dstp = em.dst[3]; base = 3 * n; }
                else {
                    i -= em.E[3];
                    if (i >= em.E[4]) return;
                    dstp = em.dst[4]; base = 4 * n;
                }
            }
        }
    }
    atomicAdd(&g_deg[base + __ldg(&dstp[i])], 1);
}

// ---------------------------------------------------------------------------
// 2) alloc: segment offsets via block scan + one global atomic.
//    Offsets CONTIGUOUS within each 256-gw scan block (16 | 256 load-bearing).
// ---------------------------------------------------------------------------
__global__ void alloc_kernel(int nelem)
{
    __shared__ int wsum[8];
    int tid  = threadIdx.x;
    int i    = blockIdx.x * 256 + tid;
    int lane = tid & 31;
    int w    = tid >> 5;

    int d = (i < nelem) ? g_deg[i] : 0;
    int v = d;
#pragma unroll
    for (int o = 1; o < 32; o <<= 1) {
        int t = __shfl_up_sync(0xffffffffu, v, o);
        if (lane >= o) v += t;
    }
    if (lane == 31) wsum[w] = v;
    __syncthreads();
    if (tid == 0) {
        int s = 0;
#pragma unroll
        for (int j = 0; j < 8; j++) { int t = wsum[j]; wsum[j] = s; s += t; }
        int b = atomicAdd(&g_total, s);
#pragma unroll
        for (int j = 0; j < 8; j++) wsum[j] += b;
    }
    __syncthreads();
    int off = wsum[w] + v - d;
    if (i < nelem) { g_off[i] = off; g_cur[i] = off; }
}

// ---------------------------------------------------------------------------
// 3) fill CSR: src and edge_id into separate arrays
// ---------------------------------------------------------------------------
__global__ void fill_kernel(EdgeMeta em, int n)
{
    int et = blockIdx.y;
    int i  = blockIdx.x * blockDim.x + threadIdx.x;
    const int* dst = (et == 0) ? em.dst[0] : (et == 1) ? em.dst[1] : (et == 2) ? em.dst[2]
                   : (et == 3) ? em.dst[3] : em.dst[4];
    const int* src = (et == 0) ? em.src[0] : (et == 1) ? em.src[1] : (et == 2) ? em.src[2]
                   : (et == 3) ? em.src[3] : em.src[4];
    if (i < em.E[et]) {
        int d = __ldg(&dst[i]);
        int s = __ldg(&src[i]);
        int pos = atomicAdd(&g_cur[et * n + d], 1);
        g_csr_src[pos] = s;
        g_csr_eid[pos] = i;
    }
}

// ---------------------------------------------------------------------------
// 4) aggregate: block-cooperative smem staging, 16 nodes/block, 2 nodes/warp.
//    Role by block parity. Inner loops issue explicit clamped-index load
//    batches (4x LDG.128 / 8x LDG.32 in flight) for MLP.
// ---------------------------------------------------------------------------
__global__ void __launch_bounds__(256, 6)
aggregate_kernel(EdgeMeta em, int n)
{
    __shared__ int s_off[G];
    __shared__ int s_deg[G];
    __shared__ int s_idx[CHUNK];

    int tid  = threadIdx.x;
    int lane = tid & 31;
    int wib  = tid >> 5;
    int role = blockIdx.x & 1;
    int gwb  = (blockIdx.x >> 1) * G;
    int nelem = NET * n;
    int nv   = min(G, nelem - gwb);
    if (nv <= 0) return;

    if (tid < nv) {
        s_off[tid] = g_off[gwb + tid];
        s_deg[tid] = g_deg[gwb + tid];
    }
    __syncthreads();

    int rbeg = s_off[0];
    int rend = s_off[nv - 1] + s_deg[nv - 1];

    int half = lane >> 4;
    int ql   = lane & 15;

    // per-warp accumulators for its 2 nodes
    __half2 acc[2][4];
    float   facc[2];
    __half2 hz = __floats2half2_rn(0.f, 0.f);
#pragma unroll
    for (int m = 0; m < 2; m++) {
        facc[m] = 0.f;
#pragma unroll
        for (int k = 0; k < 4; k++) acc[m][k] = hz;
    }

    for (int cb = rbeg; cb < rend; cb += CHUNK) {
        int clen = min(CHUNK, rend - cb);
        __syncthreads();
        if (role == 0) {
            for (int t = tid; t < clen; t += 256) s_idx[t] = g_csr_src[cb + t];
        } else {
            for (int t = tid; t < clen; t += 256) s_idx[t] = g_csr_eid[cb + t];
        }
        __syncthreads();

        if (role == 0) {
            // ---- x-gather: 8 edges/iter, 4 LDG.128 in flight per lane ----
#pragma unroll
            for (int m = 0; m < 2; m++) {
                int idx = wib * 2 + m;
                if (idx >= nv) break;
                int lo = max(s_off[idx], cb);
                int hi = min(s_off[idx] + s_deg[idx], cb + clen);
                for (int eb = lo; eb < hi; eb += 8) {
                    // clamped indices -> always-issued loads
                    int e0 = eb + 0 + half, e1 = eb + 2 + half;
                    int e2 = eb + 4 + half, e3 = eb + 6 + half;
                    int c0 = min(e0, hi - 1) - cb;
                    int c1 = min(e1, hi - 1) - cb;
                    int c2 = min(e2, hi - 1) - cb;
                    int c3 = min(e3, hi - 1) - cb;
                    int s0 = s_idx[c0], s1 = s_idx[c1];
                    int s2 = s_idx[c2], s3 = s_idx[c3];
                    uint4 v0 = __ldg(reinterpret_cast<const uint4*>(
                                   g_xh + (size_t)s0 * D) + ql);
                    uint4 v1 = __ldg(reinterpret_cast<const uint4*>(
                                   g_xh + (size_t)s1 * D) + ql);
                    uint4 v2 = __ldg(reinterpret_cast<const uint4*>(
                                   g_xh + (size_t)s2 * D) + ql);
                    uint4 v3 = __ldg(reinterpret_cast<const uint4*>(
                                   g_xh + (size_t)s3 * D) + ql);
                    __half2* h0 = reinterpret_cast<__half2*>(&v0);
                    __half2* h1 = reinterpret_cast<__half2*>(&v1);
                    __half2* h2 = reinterpret_cast<__half2*>(&v2);
                    __half2* h3 = reinterpret_cast<__half2*>(&v3);
                    if (e0 < hi) {
#pragma unroll
                        for (int k = 0; k < 4; k++) acc[m][k] = __hadd2(acc[m][k], h0[k]);
                    }
                    if (e1 < hi) {
#pragma unroll
                        for (int k = 0; k < 4; k++) acc[m][k] = __hadd2(acc[m][k], h1[k]);
                    }
                    if (e2 < hi) {
#pragma unroll
                        for (int k = 0; k < 4; k++) acc[m][k] = __hadd2(acc[m][k], h2[k]);
                    }
                    if (e3 < hi) {
#pragma unroll
                        for (int k = 0; k < 4; k++) acc[m][k] = __hadd2(acc[m][k], h3[k]);
                    }
                }
            }
        } else {
            // ---- ef-mean: 8 edges/iter, 8 LDG.32 in flight per lane ----
#pragma unroll
            for (int m = 0; m < 2; m++) {
                int idx = wib * 2 + m;
                if (idx >= nv) break;
                int gm  = gwb + idx;
                int etm = gm / n;
                const float* __restrict__ ef =
                    (etm == 0) ? em.ef[0] : (etm == 1) ? em.ef[1]
                  : (etm == 2) ? em.ef[2] : (etm == 3) ? em.ef[3] : em.ef[4];
                int lo = max(s_off[idx], cb);
                int hi = min(s_off[idx] + s_deg[idx], cb + clen);
                float a = facc[m];
                for (int eb = lo; eb < hi; eb += 8) {
                    float v[8];
#pragma unroll
                    for (int u = 0; u < 8; u++) {
                        int c = min(eb + u, hi - 1) - cb;
                        int eid = s_idx[c];
                        v[u] = __ldg(ef + (size_t)eid * DE + lane);
                    }
#pragma unroll
                    for (int u = 0; u < 8; u++)
                        if (eb + u < hi) a += v[u];
                }
                facc[m] = a;
            }
        }
    }

    // ---- write-out ----
    if (role == 0) {
#pragma unroll
        for (int m = 0; m < 2; m++) {
            int idx = wib * 2 + m;
            if (idx >= nv) break;
            int gm  = gwb + idx;
            int cnt = s_deg[idx];
            float inv = (cnt > 0) ? (1.0f / (float)cnt) : 0.0f;
            __half2 o[4];
#pragma unroll
            for (int k = 0; k < 4; k++) {
                unsigned u = __shfl_xor_sync(0xffffffffu,
                                 *reinterpret_cast<unsigned*>(&acc[m][k]), 16);
                __half2 s = __hadd2(acc[m][k], *reinterpret_cast<__half2*>(&u));
                float2 f = __half22float2(s);
                o[k] = __floats2half2_rn(f.x * inv, f.y * inv);
            }
            if (half == 0) {
                reinterpret_cast<uint4*>(g_S1h + (size_t)gm * D)[ql] =
                    *reinterpret_cast<uint4*>(o);
                if (ql == 0) g_mask[gm] = (cnt > 0) ? 1.0f : 0.0f;
            }
        }
    } else {
#pragma unroll
        for (int m = 0; m < 2; m++) {
            int idx = wib * 2 + m;
            if (idx >= nv) break;
            int gm  = gwb + idx;
            int cnt = s_deg[idx];
            float inv = (cnt > 0) ? (1.0f / (float)cnt) : 0.0f;
            float v  = facc[m] * inv;
            float hi = __shfl_down_sync(0xffffffffu, v, 1);
            if ((lane & 1) == 0) {
                __half2 h = __floats2half2_rn(v, hi);
                reinterpret_cast<__half2*>(g_S2h + (size_t)gm * DE)[lane >> 1] = h;
            }
        }
    }
}

// ---------------------------------------------------------------------------
// 5) fused GEMM (fp16 HMMA, fp32 accum) + epilogue + state reset (BM=64)
// ---------------------------------------------------------------------------
#define BM  64
#define SAH 168

__device__ __forceinline__ void mma_f16(float* c, const unsigned* a, const unsigned* b)
{
    asm volatile(
        "mma.sync.aligned.m16n8k16.row.col.f32.f16.f16.f32 "
        "{%0,%1,%2,%3}, {%4,%5,%6,%7}, {%8,%9}, {%0,%1,%2,%3};"
        : "+f"(c[0]), "+f"(c[1]), "+f"(c[2]), "+f"(c[3])
        : "r"(a[0]), "r"(a[1]), "r"(a[2]), "r"(a[3]),
          "r"(b[0]), "r"(b[1]));
}

__global__ void __launch_bounds__(256, 3)
gemm_epi_kernel(const float* __restrict__ x,
                const float* __restrict__ b0, const float* __restrict__ b1,
                const float* __restrict__ b2, const float* __restrict__ b3,
                const float* __restrict__ b4,
                float* __restrict__ out, int n)
{
    extern __shared__ __half sm[];
    __half* As = sm;                    // [BM][SAH]
    __half* Bs = sm + (size_t)BM * SAH; // [D][SAH]

    __shared__ float msk[NET][BM];
    __shared__ float bsm[NET][D];

    const float* bp[NET] = {b0, b1, b2, b3, b4};

    int tid  = threadIdx.x;
    int lane = tid & 31;
    int warp = tid >> 5;
    int wm   = (warp & 1) * 32;
    int wn   = (warp >> 1) * 32;
    int lrow = lane >> 2;
    int lcol = lane & 3;
    int row0 = blockIdx.x * BM;

#pragma unroll
    for (int et = 0; et < NET; et++) {
        if (tid < BM) {
            int row = row0 + tid;
            msk[et][tid] = (row < n) ? g_mask[(size_t)et * n + row] : 0.f;
        }
        if (tid < D) bsm[et][tid] = bp[et][tid];
    }

    float c[2][4][4];
#pragma unroll
    for (int s = 0; s < 2; s++)
#pragma unroll
        for (int t = 0; t < 4; t++)
#pragma unroll
            for (int r = 0; r < 4; r++) c[s][t][r] = 0.f;

    __syncthreads();

#pragma unroll 1
    for (int et = 0; et < NET; et++) {
        const __half* __restrict__ S1e = g_S1h + (size_t)et * n * D;
        const __half* __restrict__ S2e = g_S2h + (size_t)et * n * DE;
        const __half* __restrict__ Whe = g_Wh  + (size_t)et * D * KW;

#pragma unroll
        for (int t = 0; t < 5; t++) {
            int idx = tid + t * 256;
            int row = idx / 20;
            int cc  = idx % 20;
            int grow = row0 + row;
            uint4 v = make_uint4(0u, 0u, 0u, 0u);
            if (grow < n) {
                v = (cc < 16)
                  ? __ldg(reinterpret_cast<const uint4*>(S1e + (size_t)grow * D)  + cc)
                  : __ldg(reinterpret_cast<const uint4*>(S2e + (size_t)grow * DE) + (cc - 16));
            }
            *reinterpret_cast<uint4*>(As + (size_t)row * SAH + cc * 8) = v;
        }
#pragma unroll
        for (int t = 0; t < 10; t++) {
            int idx = tid + t * 256;
            int row = idx / 20;
            int cc  = idx % 20;
            uint4 v = __ldg(reinterpret_cast<const uint4*>(Whe + (size_t)row * KW) + cc);
            *reinterpret_cast<uint4*>(Bs + (size_t)row * SAH + cc * 8) = v;
        }
        __syncthreads();

#pragma unroll
        for (int kk = 0; kk < 10; kk++) {
            int k0 = kk * 16;
            unsigned a[2][4], b[4][2];
#pragma unroll
            for (int s = 0; s < 2; s++) {
                int m = wm + s * 16 + lrow;
                const __half* p0 = As + (size_t)m * SAH + k0 + 2 * lcol;
                a[s][0] = *reinterpret_cast<const unsigned*>(p0);
                a[s][1] = *reinterpret_cast<const unsigned*>(p0 + 8 * SAH);
                a[s][2] = *reinterpret_cast<const unsigned*>(p0 + 8);
                a[s][3] = *reinterpret_cast<const unsigned*>(p0 + 8 * SAH + 8);
            }
#pragma unroll
            for (int t = 0; t < 4; t++) {
                int nn = wn + t * 8 + lrow;
                const __half* p0 = Bs + (size_t)nn * SAH + k0 + 2 * lcol;
                b[t][0] = *reinterpret_cast<const unsigned*>(p0);
                b[t][1] = *reinterpret_cast<const unsigned*>(p0 + 8);
            }
#pragma unroll
            for (int s = 0; s < 2; s++)
#pragma unroll
                for (int t = 0; t < 4; t++)
                    mma_f16(c[s][t], a[s], b[t]);
        }
        __syncthreads();
    }

    // epilogue
#pragma unroll
    for (int s = 0; s < 2; s++) {
#pragma unroll
        for (int h = 0; h < 2; h++) {
            int mloc = wm + s * 16 + lrow + h * 8;
            int grow = row0 + mloc;
            if (grow >= n) continue;
            float mk[NET];
#pragma unroll
            for (int et = 0; et < NET; et++) mk[et] = msk[et][mloc];
#pragma unroll
            for (int t = 0; t < 4; t++) {
                int ncol = wn + t * 8 + lcol * 2;
                float bs0 = 0.f, bs1 = 0.f;
#pragma unroll
                for (int et = 0; et < NET; et++) {
                    if (mk[et] > 0.f) {
                        bs0 += bsm[et][ncol];
                        bs1 += bsm[et][ncol + 1];
                    }
                }
                float c0 = c[s][t][h * 2 + 0];
                float c1 = c[s][t][h * 2 + 1];
                const float* xp = x + (size_t)grow * D + ncol;
                float2 o;
                o.x = fmaxf(xp[0] + (c0 + bs0) * 0.2f, 0.f);
                o.y = fmaxf(xp[1] + (c1 + bs1) * 0.2f, 0.f);
                *reinterpret_cast<float2*>(out + (size_t)grow * D + ncol) = o;
            }
        }
    }

    // state reset for next replay: zero degrees + allocator
    int zi = blockIdx.x * blockDim.x + threadIdx.x;
    int zs = gridDim.x * blockDim.x;
    for (int z = zi; z < NET * n; z += zs) g_deg[z] = 0;
    if (zi == 0) g_total = 0;
}

// ---------------------------------------------------------------------------
extern "C" void kernel_launch(void* const* d_in, const int* in_sizes, int n_in,
                              void* d_out, int out_size)
{
    const float* x = (const float*)d_in[0];
    int n = in_sizes[0] / D;
    if (n > MAXN) return;

    EdgeMeta em;
    WPtrs wp;
    const float* b[NET];
    int maxE = 0, totE = 0;
    for (int et = 0; et < NET; et++) {
        em.ef[et]  = (const float*)d_in[1 + 5 * et + 0];
        wp.W[et]   = (const float*)d_in[1 + 5 * et + 1];
        b[et]      = (const float*)d_in[1 + 5 * et + 2];
        em.src[et] = (const int*)  d_in[1 + 5 * et + 3];
        em.dst[et] = (const int*)  d_in[1 + 5 * et + 4];
        em.E[et]   = in_sizes[1 + 5 * et + 3];
        if (em.E[et] > maxE) maxE = em.E[et];
        totE += em.E[et];
    }
    if (totE > CAP_TOTAL) return;
    float* out = (float*)d_out;

    int nelem = NET * n;

    static int smem_bytes = (BM + D) * SAH * (int)sizeof(__half);
    cudaFuncSetAttribute(gemm_epi_kernel,
                         cudaFuncAttributeMaxDynamicSharedMemorySize, smem_bytes);

    // 1) fused prep + count
    {
        int nx = n * D / 8;
        int nw = NET * D * KW;
        int work = nx + nw + totE;
        count_prep_kernel<<<(work + 255) / 256, 256>>>(x, wp, em, n, nx, nw);
    }
    // 2) alloc
    alloc_kernel<<<(nelem + 255) / 256, 256>>>(nelem);
    // 3) fill
    {
        dim3 grid((maxE + 255) / 256, NET);
        fill_kernel<<<grid, 256>>>(em, n);
    }
    // 4) block-cooperative aggregate, explicit load batching (profiled launch)
    {
        int nblk = (nelem + G - 1) / G;
        aggregate_kernel<<<2 * nblk, 256>>>(em, n);
    }
    // 5) fused GEMM + epilogue + reset
    {
        int blocks = (n + BM - 1) / BM;
        gemm_epi_kernel<<<blocks, 256, smem_bytes>>>(
            x, b[0], b[1], b[2], b[3], b[4], out, n);
    }
}

// round 16
// speedup vs baseline: 1.2560x; 1.0108x over previous
#include <cuda_runtime.h>
#include <cuda_fp16.h>
#include <cstdint>

#define D    128
#define DE   32
#define NET  5
#define MAXN 50000
#define CAP_TOTAL 4000000
#define KW   (D + DE)       // 160
#define G    16             // nodes per aggregate block (16 | 256 scan block)
#define CHUNK 1024          // smem CSR staging entries

// ---- scratch (device globals: allocation-free; bss zero-init at load) ----
__device__ __align__(16) __half g_xh [(size_t)MAXN * D];
__device__ __align__(16) __half g_S1h[(size_t)NET * MAXN * D];
__device__ __align__(16) __half g_S2h[(size_t)NET * MAXN * DE];
__device__ __align__(16) __half g_Wh [(size_t)NET * D * KW];     // fp16 weights, TRANSPOSED [et][n][k]
__device__ float  g_mask[(size_t)NET * MAXN];
__device__ int    g_deg[(size_t)NET * MAXN];          // zeroed by gemm epilogue
__device__ int    g_off[(size_t)NET * MAXN];
__device__ int    g_cur[(size_t)NET * MAXN];
__device__ int    g_csr_src[(size_t)CAP_TOTAL];
__device__ int    g_csr_eid[(size_t)CAP_TOTAL];
__device__ int    g_total;                            // zeroed by gemm epilogue

struct EdgeMeta {
    const int*   src[NET];
    const int*   dst[NET];
    const float* ef[NET];
    int          E[NET];
};
struct WPtrs { const float* W[NET]; };

// ---------------------------------------------------------------------------
// 1) fused: x->fp16 | W->fp16^T | edge count
// ---------------------------------------------------------------------------
__global__ void count_prep_kernel(const float* __restrict__ x, WPtrs wp,
                                  EdgeMeta em, int n, int nx, int nw)
{
    int i = blockIdx.x * blockDim.x + threadIdx.x;

    if (i < nx) {
        float4 v0 = __ldg(reinterpret_cast<const float4*>(x) + 2 * i);
        float4 v1 = __ldg(reinterpret_cast<const float4*>(x) + 2 * i + 1);
        __half2 h[4];
        h[0] = __floats2half2_rn(v0.x, v0.y);
        h[1] = __floats2half2_rn(v0.z, v0.w);
        h[2] = __floats2half2_rn(v1.x, v1.y);
        h[3] = __floats2half2_rn(v1.z, v1.w);
        reinterpret_cast<uint4*>(g_xh)[i] = *reinterpret_cast<uint4*>(h);
        return;
    }
    i -= nx;
    if (i < nw) {
        int et = i / (D * KW);
        int r  = i % (D * KW);
        int nn = r / KW;
        int k  = r % KW;
        const float* W = (et == 0) ? wp.W[0] : (et == 1) ? wp.W[1]
                       : (et == 2) ? wp.W[2] : (et == 3) ? wp.W[3] : wp.W[4];
        g_Wh[i] = __float2half_rn(__ldg(&W[k * D + nn]));
        return;
    }
    i -= nw;
    const int* dstp;
    int base;
    if (i < em.E[0]) { dstp = em.dst[0]; base = 0; }
    else {
        i -= em.E[0];
        if (i < em.E[1]) { dstp = em.dst[1]; base = n; }
        else {
            i -= em.E[1];
            if (i < em.E[2]) { dstp = em.dst[2]; base = 2 * n; }
            else {
                i -= em.E[2];
                if (i < em.E[3]) { dstp = em.dst[3]; base = 3 * n; }
                else {
                    i -= em.E[3];
                    if (i >= em.E[4]) return;
                    dstp = em.dst[4]; base = 4 * n;
                }
            }
        }
    }
    atomicAdd(&g_deg[base + __ldg(&dstp[i])], 1);
}

// ---------------------------------------------------------------------------
// 2) alloc: segment offsets via block scan + one global atomic.
//    Offsets CONTIGUOUS within each 256-gw scan block (16 | 256 load-bearing).
// ---------------------------------------------------------------------------
__global__ void alloc_kernel(int nelem)
{
    __shared__ int wsum[8];
    int tid  = threadIdx.x;
    int i    = blockIdx.x * 256 + tid;
    int lane = tid & 31;
    int w    = tid >> 5;

    int d = (i < nelem) ? g_deg[i] : 0;
    int v = d;
#pragma unroll
    for (int o = 1; o < 32; o <<= 1) {
        int t = __shfl_up_sync(0xffffffffu, v, o);
        if (lane >= o) v += t;
    }
    if (lane == 31) wsum[w] = v;
    __syncthreads();
    if (tid == 0) {
        int s = 0;
#pragma unroll
        for (int j = 0; j < 8; j++) { int t = wsum[j]; wsum[j] = s; s += t; }
        int b = atomicAdd(&g_total, s);
#pragma unroll
        for (int j = 0; j < 8; j++) wsum[j] += b;
    }
    __syncthreads();
    int off = wsum[w] + v - d;
    if (i < nelem) { g_off[i] = off; g_cur[i] = off; }
}

// ---------------------------------------------------------------------------
// 3) fill CSR: src and edge_id into separate arrays
// ---------------------------------------------------------------------------
__global__ void fill_kernel(EdgeMeta em, int n)
{
    int et = blockIdx.y;
    int i  = blockIdx.x * blockDim.x + threadIdx.x;
    const int* dst = (et == 0) ? em.dst[0] : (et == 1) ? em.dst[1] : (et == 2) ? em.dst[2]
                   : (et == 3) ? em.dst[3] : em.dst[4];
    const int* src = (et == 0) ? em.src[0] : (et == 1) ? em.src[1] : (et == 2) ? em.src[2]
                   : (et == 3) ? em.src[3] : em.src[4];
    if (i < em.E[et]) {
        int d = __ldg(&dst[i]);
        int s = __ldg(&src[i]);
        int pos = atomicAdd(&g_cur[et * n + d], 1);
        g_csr_src[pos] = s;
        g_csr_eid[pos] = i;
    }
}

// ---------------------------------------------------------------------------
// 4) aggregate: block-cooperative smem staging, 16 nodes/block, 2 nodes/warp.
//    Role by block parity. Inner loops issue batches of PREDICATED independent
//    loads (zero default, unconditional accumulate) — MLP without duplicate
//    tail traffic.
// ---------------------------------------------------------------------------
__global__ void __launch_bounds__(256, 6)
aggregate_kernel(EdgeMeta em, int n)
{
    __shared__ int s_off[G];
    __shared__ int s_deg[G];
    __shared__ int s_idx[CHUNK];

    int tid  = threadIdx.x;
    int lane = tid & 31;
    int wib  = tid >> 5;
    int role = blockIdx.x & 1;
    int gwb  = (blockIdx.x >> 1) * G;
    int nelem = NET * n;
    int nv   = min(G, nelem - gwb);
    if (nv <= 0) return;

    if (tid < nv) {
        s_off[tid] = g_off[gwb + tid];
        s_deg[tid] = g_deg[gwb + tid];
    }
    __syncthreads();

    int rbeg = s_off[0];
    int rend = s_off[nv - 1] + s_deg[nv - 1];

    int half = lane >> 4;
    int ql   = lane & 15;

    // per-warp accumulators for its 2 nodes
    __half2 acc[2][4];
    float   facc[2];
    __half2 hz = __floats2half2_rn(0.f, 0.f);
#pragma unroll
    for (int m = 0; m < 2; m++) {
        facc[m] = 0.f;
#pragma unroll
        for (int k = 0; k < 4; k++) acc[m][k] = hz;
    }

    for (int cb = rbeg; cb < rend; cb += CHUNK) {
        int clen = min(CHUNK, rend - cb);
        __syncthreads();
        if (role == 0) {
            for (int t = tid; t < clen; t += 256) s_idx[t] = g_csr_src[cb + t];
        } else {
            for (int t = tid; t < clen; t += 256) s_idx[t] = g_csr_eid[cb + t];
        }
        __syncthreads();

        if (role == 0) {
            // ---- x-gather: 8 edges/iter, 4 predicated LDG.128 in flight ----
#pragma unroll
            for (int m = 0; m < 2; m++) {
                int idx = wib * 2 + m;
                if (idx >= nv) break;
                int lo = max(s_off[idx], cb);
                int hi = min(s_off[idx] + s_deg[idx], cb + clen);
                for (int eb = lo; eb < hi; eb += 8) {
                    int e0 = eb + 0 + half, e1 = eb + 2 + half;
                    int e2 = eb + 4 + half, e3 = eb + 6 + half;
                    uint4 v0 = make_uint4(0u, 0u, 0u, 0u);
                    uint4 v1 = v0, v2 = v0, v3 = v0;
                    if (e0 < hi) v0 = __ldg(reinterpret_cast<const uint4*>(
                                        g_xh + (size_t)s_idx[e0 - cb] * D) + ql);
                    if (e1 < hi) v1 = __ldg(reinterpret_cast<const uint4*>(
                                        g_xh + (size_t)s_idx[e1 - cb] * D) + ql);
                    if (e2 < hi) v2 = __ldg(reinterpret_cast<const uint4*>(
                                        g_xh + (size_t)s_idx[e2 - cb] * D) + ql);
                    if (e3 < hi) v3 = __ldg(reinterpret_cast<const uint4*>(
                                        g_xh + (size_t)s_idx[e3 - cb] * D) + ql);
                    __half2* h0 = reinterpret_cast<__half2*>(&v0);
                    __half2* h1 = reinterpret_cast<__half2*>(&v1);
                    __half2* h2 = reinterpret_cast<__half2*>(&v2);
                    __half2* h3 = reinterpret_cast<__half2*>(&v3);
#pragma unroll
                    for (int k = 0; k < 4; k++) {
                        acc[m][k] = __hadd2(acc[m][k], h0[k]);
                        acc[m][k] = __hadd2(acc[m][k], h1[k]);
                        acc[m][k] = __hadd2(acc[m][k], h2[k]);
                        acc[m][k] = __hadd2(acc[m][k], h3[k]);
                    }
                }
            }
        } else {
            // ---- ef-mean: 8 edges/iter, 8 predicated LDG.32 in flight ----
#pragma unroll
            for (int m = 0; m < 2; m++) {
                int idx = wib * 2 + m;
                if (idx >= nv) break;
                int gm  = gwb + idx;
                int etm = gm / n;
                const float* __restrict__ ef =
                    (etm == 0) ? em.ef[0] : (etm == 1) ? em.ef[1]
                  : (etm == 2) ? em.ef[2] : (etm == 3) ? em.ef[3] : em.ef[4];
                int lo = max(s_off[idx], cb);
                int hi = min(s_off[idx] + s_deg[idx], cb + clen);
                float a = facc[m];
                for (int eb = lo; eb < hi; eb += 8) {
                    float v[8];
#pragma unroll
                    for (int u = 0; u < 8; u++) {
                        v[u] = 0.f;
                        int e = eb + u;
                        if (e < hi)
                            v[u] = __ldg(ef + (size_t)s_idx[e - cb] * DE + lane);
                    }
                    a += ((v[0] + v[1]) + (v[2] + v[3]))
                       + ((v[4] + v[5]) + (v[6] + v[7]));
                }
                facc[m] = a;
            }
        }
    }

    // ---- write-out ----
    if (role == 0) {
#pragma unroll
        for (int m = 0; m < 2; m++) {
            int idx = wib * 2 + m;
            if (idx >= nv) break;
            int gm  = gwb + idx;
            int cnt = s_deg[idx];
            float inv = (cnt > 0) ? (1.0f / (float)cnt) : 0.0f;
            __half2 o[4];
#pragma unroll
            for (int k = 0; k < 4; k++) {
                unsigned u = __shfl_xor_sync(0xffffffffu,
                                 *reinterpret_cast<unsigned*>(&acc[m][k]), 16);
                __half2 s = __hadd2(acc[m][k], *reinterpret_cast<__half2*>(&u));
                float2 f = __half22float2(s);
                o[k] = __floats2half2_rn(f.x * inv, f.y * inv);
            }
            if (half == 0) {
                reinterpret_cast<uint4*>(g_S1h + (size_t)gm * D)[ql] =
                    *reinterpret_cast<uint4*>(o);
                if (ql == 0) g_mask[gm] = (cnt > 0) ? 1.0f : 0.0f;
            }
        }
    } else {
#pragma unroll
        for (int m = 0; m < 2; m++) {
            int idx = wib * 2 + m;
            if (idx >= nv) break;
            int gm  = gwb + idx;
            int cnt = s_deg[idx];
            float inv = (cnt > 0) ? (1.0f / (float)cnt) : 0.0f;
            float v  = facc[m] * inv;
            float hi = __shfl_down_sync(0xffffffffu, v, 1);
            if ((lane & 1) == 0) {
                __half2 h = __floats2half2_rn(v, hi);
                reinterpret_cast<__half2*>(g_S2h + (size_t)gm * DE)[lane >> 1] = h;
            }
        }
    }
}

// ---------------------------------------------------------------------------
// 5) fused GEMM (fp16 HMMA, fp32 accum) + epilogue + state reset (BM=64)
// ---------------------------------------------------------------------------
#define BM  64
#define SAH 168

__device__ __forceinline__ void mma_f16(float* c, const unsigned* a, const unsigned* b)
{
    asm volatile(
        "mma.sync.aligned.m16n8k16.row.col.f32.f16.f16.f32 "
        "{%0,%1,%2,%3}, {%4,%5,%6,%7}, {%8,%9}, {%0,%1,%2,%3};"
        : "+f"(c[0]), "+f"(c[1]), "+f"(c[2]), "+f"(c[3])
        : "r"(a[0]), "r"(a[1]), "r"(a[2]), "r"(a[3]),
          "r"(b[0]), "r"(b[1]));
}

__global__ void __launch_bounds__(256, 3)
gemm_epi_kernel(const float* __restrict__ x,
                const float* __restrict__ b0, const float* __restrict__ b1,
                const float* __restrict__ b2, const float* __restrict__ b3,
                const float* __restrict__ b4,
                float* __restrict__ out, int n)
{
    extern __shared__ __half sm[];
    __half* As = sm;                    // [BM][SAH]
    __half* Bs = sm + (size_t)BM * SAH; // [D][SAH]

    __shared__ float msk[NET][BM];
    __shared__ float bsm[NET][D];

    const float* bp[NET] = {b0, b1, b2, b3, b4};

    int tid  = threadIdx.x;
    int lane = tid & 31;
    int warp = tid >> 5;
    int wm   = (warp & 1) * 32;
    int wn   = (warp >> 1) * 32;
    int lrow = lane >> 2;
    int lcol = lane & 3;
    int row0 = blockIdx.x * BM;

#pragma unroll
    for (int et = 0; et < NET; et++) {
        if (tid < BM) {
            int row = row0 + tid;
            msk[et][tid] = (row < n) ? g_mask[(size_t)et * n + row] : 0.f;
        }
        if (tid < D) bsm[et][tid] = bp[et][tid];
    }

    float c[2][4][4];
#pragma unroll
    for (int s = 0; s < 2; s++)
#pragma unroll
        for (int t = 0; t < 4; t++)
#pragma unroll
            for (int r = 0; r < 4; r++) c[s][t][r] = 0.f;

    __syncthreads();

#pragma unroll 1
    for (int et = 0; et < NET; et++) {
        const __half* __restrict__ S1e = g_S1h + (size_t)et * n * D;
        const __half* __restrict__ S2e = g_S2h + (size_t)et * n * DE;
        const __half* __restrict__ Whe = g_Wh  + (size_t)et * D * KW;

#pragma unroll
        for (int t = 0; t < 5; t++) {
            int idx = tid + t * 256;
            int row = idx / 20;
            int cc  = idx % 20;
            int grow = row0 + row;
            uint4 v = make_uint4(0u, 0u, 0u, 0u);
            if (grow < n) {
                v = (cc < 16)
                  ? __ldg(reinterpret_cast<const uint4*>(S1e + (size_t)grow * D)  + cc)
                  : __ldg(reinterpret_cast<const uint4*>(S2e + (size_t)grow * DE) + (cc - 16));
            }
            *reinterpret_cast<uint4*>(As + (size_t)row * SAH + cc * 8) = v;
        }
#pragma unroll
        for (int t = 0; t < 10; t++) {
            int idx = tid + t * 256;
            int row = idx / 20;
            int cc  = idx % 20;
            uint4 v = __ldg(reinterpret_cast<const uint4*>(Whe + (size_t)row * KW) + cc);
            *reinterpret_cast<uint4*>(Bs + (size_t)row * SAH + cc * 8) = v;
        }
        __syncthreads();

#pragma unroll
        for (int kk = 0; kk < 10; kk++) {
            int k0 = kk * 16;
            unsigned a[2][4], b[4][2];
#pragma unroll
            for (int s = 0; s < 2; s++) {
                int m = wm + s * 16 + lrow;
                const __half* p0 = As + (size_t)m * SAH + k0 + 2 * lcol;
                a[s][0] = *reinterpret_cast<const unsigned*>(p0);
                a[s][1] = *reinterpret_cast<const unsigned*>(p0 + 8 * SAH);
                a[s][2] = *reinterpret_cast<const unsigned*>(p0 + 8);
                a[s][3] = *reinterpret_cast<const unsigned*>(p0 + 8 * SAH + 8);
            }
#pragma unroll
            for (int t = 0; t < 4; t++) {
                int nn = wn + t * 8 + lrow;
                const __half* p0 = Bs + (size_t)nn * SAH + k0 + 2 * lcol;
                b[t][0] = *reinterpret_cast<const unsigned*>(p0);
                b[t][1] = *reinterpret_cast<const unsigned*>(p0 + 8);
            }
#pragma unroll
            for (int s = 0; s < 2; s++)
#pragma unroll
                for (int t = 0; t < 4; t++)
                    mma_f16(c[s][t], a[s], b[t]);
        }
        __syncthreads();
    }

    // epilogue
#pragma unroll
    for (int s = 0; s < 2; s++) {
#pragma unroll
        for (int h = 0; h < 2; h++) {
            int mloc = wm + s * 16 + lrow + h * 8;
            int grow = row0 + mloc;
            if (grow >= n) continue;
            float mk[NET];
#pragma unroll
            for (int et = 0; et < NET; et++) mk[et] = msk[et][mloc];
#pragma unroll
            for (int t = 0; t < 4; t++) {
                int ncol = wn + t * 8 + lcol * 2;
                float bs0 = 0.f, bs1 = 0.f;
#pragma unroll
                for (int et = 0; et < NET; et++) {
                    if (mk[et] > 0.f) {
                        bs0 += bsm[et][ncol];
                        bs1 += bsm[et][ncol + 1];
                    }
                }
                float c0 = c[s][t][h * 2 + 0];
                float c1 = c[s][t][h * 2 + 1];
                const float* xp = x + (size_t)grow * D + ncol;
                float2 o;
                o.x = fmaxf(xp[0] + (c0 + bs0) * 0.2f, 0.f);
                o.y = fmaxf(xp[1] + (c1 + bs1) * 0.2f, 0.f);
                *reinterpret_cast<float2*>(out + (size_t)grow * D + ncol) = o;
            }
        }
    }

    // state reset for next replay: zero degrees + allocator
    int zi = blockIdx.x * blockDim.x + threadIdx.x;
    int zs = gridDim.x * blockDim.x;
    for (int z = zi; z < NET * n; z += zs) g_deg[z] = 0;
    if (zi == 0) g_total = 0;
}

// ---------------------------------------------------------------------------
extern "C" void kernel_launch(void* const* d_in, const int* in_sizes, int n_in,
                              void* d_out, int out_size)
{
    const float* x = (const float*)d_in[0];
    int n = in_sizes[0] / D;
    if (n > MAXN) return;

    EdgeMeta em;
    WPtrs wp;
    const float* b[NET];
    int maxE = 0, totE = 0;
    for (int et = 0; et < NET; et++) {
        em.ef[et]  = (const float*)d_in[1 + 5 * et + 0];
        wp.W[et]   = (const float*)d_in[1 + 5 * et + 1];
        b[et]      = (const float*)d_in[1 + 5 * et + 2];
        em.src[et] = (const int*)  d_in[1 + 5 * et + 3];
        em.dst[et] = (const int*)  d_in[1 + 5 * et + 4];
        em.E[et]   = in_sizes[1 + 5 * et + 3];
        if (em.E[et] > maxE) maxE = em.E[et];
        totE += em.E[et];
    }
    if (totE > CAP_TOTAL) return;
    float* out = (float*)d_out;

    int nelem = NET * n;

    static int smem_bytes = (BM + D) * SAH * (int)sizeof(__half);
    cudaFuncSetAttribute(gemm_epi_kernel,
                         cudaFuncAttributeMaxDynamicSharedMemorySize, smem_bytes);

    // 1) fused prep + count
    {
        int nx = n * D / 8;
        int nw = NET * D * KW;
        int work = nx + nw + totE;
        count_prep_kernel<<<(work + 255) / 256, 256>>>(x, wp, em, n, nx, nw);
    }
    // 2) alloc
    alloc_kernel<<<(nelem + 255) / 256, 256>>>(nelem);
    // 3) fill
    {
        dim3 grid((maxE + 255) / 256, NET);
        fill_kernel<<<grid, 256>>>(em, n);
    }
    // 4) block-cooperative aggregate, predicated load batches (profiled launch)
    {
        int nblk = (nelem + G - 1) / G;
        aggregate_kernel<<<2 * nblk, 256>>>(em, n);
    }
    // 5) fused GEMM + epilogue + reset
    {
        int blocks = (n + BM - 1) / BM;
        gemm_epi_kernel<<<blocks, 256, smem_bytes>>>(
            x, b[0], b[1], b[2], b[3], b[4], out, n);
    }
}

// round 17
// speedup vs baseline: 1.2838x; 1.0222x over previous
#include <cuda_runtime.h>
#include <cuda_fp16.h>
#include <cstdint>

#define D    128
#define DE   32
#define NET  5
#define MAXN 50000
#define CAP_TOTAL 4000000
#define KW   (D + DE)       // 160
#define G    16             // nodes per aggregate block (16 | 256 scan block)
#define CHUNK 1024          // smem CSR staging entries

// ---- scratch (device globals: allocation-free; bss zero-init at load) ----
__device__ __align__(16) __half g_xh [(size_t)MAXN * D];
__device__ __align__(16) __half g_S1h[(size_t)NET * MAXN * D];
__device__ __align__(16) __half g_S2h[(size_t)NET * MAXN * DE];
__device__ __align__(16) __half g_Wh [(size_t)NET * D * KW];     // fp16 weights, TRANSPOSED [et][n][k]
__device__ float  g_mask[(size_t)NET * MAXN];
__device__ int    g_deg[(size_t)NET * MAXN];          // zeroed by gemm epilogue
__device__ int    g_off[(size_t)NET * MAXN];
__device__ int    g_cur[(size_t)NET * MAXN];
__device__ int    g_csr_src[(size_t)CAP_TOTAL];
__device__ int    g_csr_eid[(size_t)CAP_TOTAL];
__device__ int    g_total;                            // zeroed by gemm epilogue

struct EdgeMeta {
    const int*   src[NET];
    const int*   dst[NET];
    const float* ef[NET];
    int          E[NET];
};
struct WPtrs { const float* W[NET]; };

// ---------------------------------------------------------------------------
// 1) fused: x->fp16 | W->fp16^T | edge count
// ---------------------------------------------------------------------------
__global__ void count_prep_kernel(const float* __restrict__ x, WPtrs wp,
                                  EdgeMeta em, int n, int nx, int nw)
{
    int i = blockIdx.x * blockDim.x + threadIdx.x;

    if (i < nx) {
        float4 v0 = __ldg(reinterpret_cast<const float4*>(x) + 2 * i);
        float4 v1 = __ldg(reinterpret_cast<const float4*>(x) + 2 * i + 1);
        __half2 h[4];
        h[0] = __floats2half2_rn(v0.x, v0.y);
        h[1] = __floats2half2_rn(v0.z, v0.w);
        h[2] = __floats2half2_rn(v1.x, v1.y);
        h[3] = __floats2half2_rn(v1.z, v1.w);
        reinterpret_cast<uint4*>(g_xh)[i] = *reinterpret_cast<uint4*>(h);
        return;
    }
    i -= nx;
    if (i < nw) {
        int et = i / (D * KW);
        int r  = i % (D * KW);
        int nn = r / KW;
        int k  = r % KW;
        const float* W = (et == 0) ? wp.W[0] : (et == 1) ? wp.W[1]
                       : (et == 2) ? wp.W[2] : (et == 3) ? wp.W[3] : wp.W[4];
        g_Wh[i] = __float2half_rn(__ldg(&W[k * D + nn]));
        return;
    }
    i -= nw;
    const int* dstp;
    int base;
    if (i < em.E[0]) { dstp = em.dst[0]; base = 0; }
    else {
        i -= em.E[0];
        if (i < em.E[1]) { dstp = em.dst[1]; base = n; }
        else {
            i -= em.E[1];
            if (i < em.E[2]) { dstp = em.dst[2]; base = 2 * n; }
            else {
                i -= em.E[2];
                if (i < em.E[3]) { dstp = em.dst[3]; base = 3 * n; }
                else {
                    i -= em.E[3];
                    if (i >= em.E[4]) return;
                    dstp = em.dst[4]; base = 4 * n;
                }
            }
        }
    }
    atomicAdd(&g_deg[base + __ldg(&dstp[i])], 1);
}

// ---------------------------------------------------------------------------
// 2) alloc: segment offsets via block scan + one global atomic.
//    Offsets CONTIGUOUS within each 256-gw scan block (16 | 256 load-bearing).
// ---------------------------------------------------------------------------
__global__ void alloc_kernel(int nelem)
{
    __shared__ int wsum[8];
    int tid  = threadIdx.x;
    int i    = blockIdx.x * 256 + tid;
    int lane = tid & 31;
    int w    = tid >> 5;

    int d = (i < nelem) ? g_deg[i] : 0;
    int v = d;
#pragma unroll
    for (int o = 1; o < 32; o <<= 1) {
        int t = __shfl_up_sync(0xffffffffu, v, o);
        if (lane >= o) v += t;
    }
    if (lane == 31) wsum[w] = v;
    __syncthreads();
    if (tid == 0) {
        int s = 0;
#pragma unroll
        for (int j = 0; j < 8; j++) { int t = wsum[j]; wsum[j] = s; s += t; }
        int b = atomicAdd(&g_total, s);
#pragma unroll
        for (int j = 0; j < 8; j++) wsum[j] += b;
    }
    __syncthreads();
    int off = wsum[w] + v - d;
    if (i < nelem) { g_off[i] = off; g_cur[i] = off; }
}

// ---------------------------------------------------------------------------
// 3) fill CSR: src and edge_id into separate arrays
// ---------------------------------------------------------------------------
__global__ void fill_kernel(EdgeMeta em, int n)
{
    int et = blockIdx.y;
    int i  = blockIdx.x * blockDim.x + threadIdx.x;
    const int* dst = (et == 0) ? em.dst[0] : (et == 1) ? em.dst[1] : (et == 2) ? em.dst[2]
                   : (et == 3) ? em.dst[3] : em.dst[4];
    const int* src = (et == 0) ? em.src[0] : (et == 1) ? em.src[1] : (et == 2) ? em.src[2]
                   : (et == 3) ? em.src[3] : em.src[4];
    if (i < em.E[et]) {
        int d = __ldg(&dst[i]);
        int s = __ldg(&src[i]);
        int pos = atomicAdd(&g_cur[et * n + d], 1);
        g_csr_src[pos] = s;
        g_csr_eid[pos] = i;
    }
}

// ---------------------------------------------------------------------------
// 4) ef-mean: block-staged, float4 loads (8 lanes/edge, 4 edge-groups/warp).
//    2 nodes/warp; 8 edges in flight (2 predicated float4 loads per lane).
// ---------------------------------------------------------------------------
__global__ void __launch_bounds__(256, 6)
efmean_kernel(EdgeMeta em, int n)
{
    __shared__ int s_off[G];
    __shared__ int s_deg[G];
    __shared__ int s_idx[CHUNK];

    int tid  = threadIdx.x;
    int lane = tid & 31;
    int wib  = tid >> 5;
    int gwb  = blockIdx.x * G;
    int nelem = NET * n;
    int nv   = min(G, nelem - gwb);
    if (nv <= 0) return;

    if (tid < nv) {
        s_off[tid] = g_off[gwb + tid];
        s_deg[tid] = g_deg[gwb + tid];
    }
    __syncthreads();

    int rbeg = s_off[0];
    int rend = s_off[nv - 1] + s_deg[nv - 1];

    int q   = lane >> 3;   // edge group 0..3
    int ql8 = lane & 7;    // float4 index within 128B row

    float4 a4[2];
#pragma unroll
    for (int m = 0; m < 2; m++) a4[m] = make_float4(0.f, 0.f, 0.f, 0.f);

    for (int cb = rbeg; cb < rend; cb += CHUNK) {
        int clen = min(CHUNK, rend - cb);
        __syncthreads();
        for (int t = tid; t < clen; t += 256) s_idx[t] = g_csr_eid[cb + t];
        __syncthreads();

#pragma unroll
        for (int m = 0; m < 2; m++) {
            int idx = wib * 2 + m;
            if (idx >= nv) break;
            int gm  = gwb + idx;
            int etm = gm / n;
            const float* __restrict__ ef =
                (etm == 0) ? em.ef[0] : (etm == 1) ? em.ef[1]
              : (etm == 2) ? em.ef[2] : (etm == 3) ? em.ef[3] : em.ef[4];
            int lo = max(s_off[idx], cb);
            int hi = min(s_off[idx] + s_deg[idx], cb + clen);
            float4 a = a4[m];
            for (int eb = lo; eb < hi; eb += 8) {
                int e0 = eb + q, e1 = eb + 4 + q;
                float4 v0 = make_float4(0.f, 0.f, 0.f, 0.f);
                float4 v1 = v0;
                if (e0 < hi) v0 = __ldg(reinterpret_cast<const float4*>(
                                      ef + (size_t)s_idx[e0 - cb] * DE) + ql8);
                if (e1 < hi) v1 = __ldg(reinterpret_cast<const float4*>(
                                      ef + (size_t)s_idx[e1 - cb] * DE) + ql8);
                a.x += v0.x + v1.x;
                a.y += v0.y + v1.y;
                a.z += v0.z + v1.z;
                a.w += v0.w + v1.w;
            }
            a4[m] = a;
        }
    }

    // combine the 4 edge-groups (same ql8 across q) and write fp16 means
#pragma unroll
    for (int m = 0; m < 2; m++) {
        int idx = wib * 2 + m;
        if (idx >= nv) break;
        int gm  = gwb + idx;
        int cnt = s_deg[idx];
        float inv = (cnt > 0) ? (1.0f / (float)cnt) : 0.0f;
        float4 a = a4[m];
#pragma unroll
        for (int o = 8; o <= 16; o <<= 1) {
            a.x += __shfl_xor_sync(0xffffffffu, a.x, o);
            a.y += __shfl_xor_sync(0xffffffffu, a.y, o);
            a.z += __shfl_xor_sync(0xffffffffu, a.z, o);
            a.w += __shfl_xor_sync(0xffffffffu, a.w, o);
        }
        if (q == 0) {
            __half2 h0 = __floats2half2_rn(a.x * inv, a.y * inv);
            __half2 h1 = __floats2half2_rn(a.z * inv, a.w * inv);
            uint2 u;
            u.x = *reinterpret_cast<unsigned*>(&h0);
            u.y = *reinterpret_cast<unsigned*>(&h1);
            reinterpret_cast<uint2*>(g_S2h + (size_t)gm * DE)[ql8] = u;
        }
    }
}

// ---------------------------------------------------------------------------
// 5) x-gather: block-staged, 16 nodes/block, 2 nodes/warp, 8 edges/iter
//    (4 predicated LDG.128 in flight). fp16 HADD2 accumulation.
// ---------------------------------------------------------------------------
__global__ void __launch_bounds__(256, 6)
gather_kernel(int n)
{
    __shared__ int s_off[G];
    __shared__ int s_deg[G];
    __shared__ int s_idx[CHUNK];

    int tid  = threadIdx.x;
    int lane = tid & 31;
    int wib  = tid >> 5;
    int gwb  = blockIdx.x * G;
    int nelem = NET * n;
    int nv   = min(G, nelem - gwb);
    if (nv <= 0) return;

    if (tid < nv) {
        s_off[tid] = g_off[gwb + tid];
        s_deg[tid] = g_deg[gwb + tid];
    }
    __syncthreads();

    int rbeg = s_off[0];
    int rend = s_off[nv - 1] + s_deg[nv - 1];

    int half = lane >> 4;
    int ql   = lane & 15;

    __half2 acc[2][4];
    __half2 hz = __floats2half2_rn(0.f, 0.f);
#pragma unroll
    for (int m = 0; m < 2; m++)
#pragma unroll
        for (int k = 0; k < 4; k++) acc[m][k] = hz;

    for (int cb = rbeg; cb < rend; cb += CHUNK) {
        int clen = min(CHUNK, rend - cb);
        __syncthreads();
        for (int t = tid; t < clen; t += 256) s_idx[t] = g_csr_src[cb + t];
        __syncthreads();

#pragma unroll
        for (int m = 0; m < 2; m++) {
            int idx = wib * 2 + m;
            if (idx >= nv) break;
            int lo = max(s_off[idx], cb);
            int hi = min(s_off[idx] + s_deg[idx], cb + clen);
            for (int eb = lo; eb < hi; eb += 8) {
                int e0 = eb + 0 + half, e1 = eb + 2 + half;
                int e2 = eb + 4 + half, e3 = eb + 6 + half;
                uint4 v0 = make_uint4(0u, 0u, 0u, 0u);
                uint4 v1 = v0, v2 = v0, v3 = v0;
                if (e0 < hi) v0 = __ldg(reinterpret_cast<const uint4*>(
                                    g_xh + (size_t)s_idx[e0 - cb] * D) + ql);
                if (e1 < hi) v1 = __ldg(reinterpret_cast<const uint4*>(
                                    g_xh + (size_t)s_idx[e1 - cb] * D) + ql);
                if (e2 < hi) v2 = __ldg(reinterpret_cast<const uint4*>(
                                    g_xh + (size_t)s_idx[e2 - cb] * D) + ql);
                if (e3 < hi) v3 = __ldg(reinterpret_cast<const uint4*>(
                                    g_xh + (size_t)s_idx[e3 - cb] * D) + ql);
                __half2* h0 = reinterpret_cast<__half2*>(&v0);
                __half2* h1 = reinterpret_cast<__half2*>(&v1);
                __half2* h2 = reinterpret_cast<__half2*>(&v2);
                __half2* h3 = reinterpret_cast<__half2*>(&v3);
#pragma unroll
                for (int k = 0; k < 4; k++) {
                    acc[m][k] = __hadd2(acc[m][k], h0[k]);
                    acc[m][k] = __hadd2(acc[m][k], h1[k]);
                    acc[m][k] = __hadd2(acc[m][k], h2[k]);
                    acc[m][k] = __hadd2(acc[m][k], h3[k]);
                }
            }
        }
    }

#pragma unroll
    for (int m = 0; m < 2; m++) {
        int idx = wib * 2 + m;
        if (idx >= nv) break;
        int gm  = gwb + idx;
        int cnt = s_deg[idx];
        float inv = (cnt > 0) ? (1.0f / (float)cnt) : 0.0f;
        __half2 o[4];
#pragma unroll
        for (int k = 0; k < 4; k++) {
            unsigned u = __shfl_xor_sync(0xffffffffu,
                             *reinterpret_cast<unsigned*>(&acc[m][k]), 16);
            __half2 s = __hadd2(acc[m][k], *reinterpret_cast<__half2*>(&u));
            float2 f = __half22float2(s);
            o[k] = __floats2half2_rn(f.x * inv, f.y * inv);
        }
        if (half == 0) {
            reinterpret_cast<uint4*>(g_S1h + (size_t)gm * D)[ql] =
                *reinterpret_cast<uint4*>(o);
            if (ql == 0) g_mask[gm] = (cnt > 0) ? 1.0f : 0.0f;
        }
    }
}

// ---------------------------------------------------------------------------
// 6) fused GEMM (fp16 HMMA, fp32 accum) + epilogue + state reset (BM=64)
// ---------------------------------------------------------------------------
#define BM  64
#define SAH 168

__device__ __forceinline__ void mma_f16(float* c, const unsigned* a, const unsigned* b)
{
    asm volatile(
        "mma.sync.aligned.m16n8k16.row.col.f32.f16.f16.f32 "
        "{%0,%1,%2,%3}, {%4,%5,%6,%7}, {%8,%9}, {%0,%1,%2,%3};"
        : "+f"(c[0]), "+f"(c[1]), "+f"(c[2]), "+f"(c[3])
        : "r"(a[0]), "r"(a[1]), "r"(a[2]), "r"(a[3]),
          "r"(b[0]), "r"(b[1]));
}

__global__ void __launch_bounds__(256, 3)
gemm_epi_kernel(const float* __restrict__ x,
                const float* __restrict__ b0, const float* __restrict__ b1,
                const float* __restrict__ b2, const float* __restrict__ b3,
                const float* __restrict__ b4,
                float* __restrict__ out, int n)
{
    extern __shared__ __half sm[];
    __half* As = sm;                    // [BM][SAH]
    __half* Bs = sm + (size_t)BM * SAH; // [D][SAH]

    __shared__ float msk[NET][BM];
    __shared__ float bsm[NET][D];

    const float* bp[NET] = {b0, b1, b2, b3, b4};

    int tid  = threadIdx.x;
    int lane = tid & 31;
    int warp = tid >> 5;
    int wm   = (warp & 1) * 32;
    int wn   = (warp >> 1) * 32;
    int lrow = lane >> 2;
    int lcol = lane & 3;
    int row0 = blockIdx.x * BM;

#pragma unroll
    for (int et = 0; et < NET; et++) {
        if (tid < BM) {
            int row = row0 + tid;
            msk[et][tid] = (row < n) ? g_mask[(size_t)et * n + row] : 0.f;
        }
        if (tid < D) bsm[et][tid] = bp[et][tid];
    }

    float c[2][4][4];
#pragma unroll
    for (int s = 0; s < 2; s++)
#pragma unroll
        for (int t = 0; t < 4; t++)
#pragma unroll
            for (int r = 0; r < 4; r++) c[s][t][r] = 0.f;

    __syncthreads();

#pragma unroll 1
    for (int et = 0; et < NET; et++) {
        const __half* __restrict__ S1e = g_S1h + (size_t)et * n * D;
        const __half* __restrict__ S2e = g_S2h + (size_t)et * n * DE;
        const __half* __restrict__ Whe = g_Wh  + (size_t)et * D * KW;

#pragma unroll
        for (int t = 0; t < 5; t++) {
            int idx = tid + t * 256;
            int row = idx / 20;
            int cc  = idx % 20;
            int grow = row0 + row;
            uint4 v = make_uint4(0u, 0u, 0u, 0u);
            if (grow < n) {
                v = (cc < 16)
                  ? __ldg(reinterpret_cast<const uint4*>(S1e + (size_t)grow * D)  + cc)
                  : __ldg(reinterpret_cast<const uint4*>(S2e + (size_t)grow * DE) + (cc - 16));
            }
            *reinterpret_cast<uint4*>(As + (size_t)row * SAH + cc * 8) = v;
        }
#pragma unroll
        for (int t = 0; t < 10; t++) {
            int idx = tid + t * 256;
            int row = idx / 20;
            int cc  = idx % 20;
            uint4 v = __ldg(reinterpret_cast<const uint4*>(Whe + (size_t)row * KW) + cc);
            *reinterpret_cast<uint4*>(Bs + (size_t)row * SAH + cc * 8) = v;
        }
        __syncthreads();

#pragma unroll
        for (int kk = 0; kk < 10; kk++) {
            int k0 = kk * 16;
            unsigned a[2][4], b[4][2];
#pragma unroll
            for (int s = 0; s < 2; s++) {
                int m = wm + s * 16 + lrow;
                const __half* p0 = As + (size_t)m * SAH + k0 + 2 * lcol;
                a[s][0] = *reinterpret_cast<const unsigned*>(p0);
                a[s][1] = *reinterpret_cast<const unsigned*>(p0 + 8 * SAH);
                a[s][2] = *reinterpret_cast<const unsigned*>(p0 + 8);
                a[s][3] = *reinterpret_cast<const unsigned*>(p0 + 8 * SAH + 8);
            }
#pragma unroll
            for (int t = 0; t < 4; t++) {
                int nn = wn + t * 8 + lrow;
                const __half* p0 = Bs + (size_t)nn * SAH + k0 + 2 * lcol;
                b[t][0] = *reinterpret_cast<const unsigned*>(p0);
                b[t][1] = *reinterpret_cast<const unsigned*>(p0 + 8);
            }
#pragma unroll
            for (int s = 0; s < 2; s++)
#pragma unroll
                for (int t = 0; t < 4; t++)
                    mma_f16(c[s][t], a[s], b[t]);
        }
        __syncthreads();
    }

    // epilogue
#pragma unroll
    for (int s = 0; s < 2; s++) {
#pragma unroll
        for (int h = 0; h < 2; h++) {
            int mloc = wm + s * 16 + lrow + h * 8;
            int grow = row0 + mloc;
            if (grow >= n) continue;
            float mk[NET];
#pragma unroll
            for (int et = 0; et < NET; et++) mk[et] = msk[et][mloc];
#pragma unroll
            for (int t = 0; t < 4; t++) {
                int ncol = wn + t * 8 + lcol * 2;
                float bs0 = 0.f, bs1 = 0.f;
#pragma unroll
                for (int et = 0; et < NET; et++) {
                    if (mk[et] > 0.f) {
                        bs0 += bsm[et][ncol];
                        bs1 += bsm[et][ncol + 1];
                    }
                }
                float c0 = c[s][t][h * 2 + 0];
                float c1 = c[s][t][h * 2 + 1];
                const float* xp = x + (size_t)grow * D + ncol;
                float2 o;
                o.x = fmaxf(xp[0] + (c0 + bs0) * 0.2f, 0.f);
                o.y = fmaxf(xp[1] + (c1 + bs1) * 0.2f, 0.f);
                *reinterpret_cast<float2*>(out + (size_t)grow * D + ncol) = o;
            }
        }
    }

    // state reset for next replay: zero degrees + allocator
    int zi = blockIdx.x * blockDim.x + threadIdx.x;
    int zs = gridDim.x * blockDim.x;
    for (int z = zi; z < NET * n; z += zs) g_deg[z] = 0;
    if (zi == 0) g_total = 0;
}

// ---------------------------------------------------------------------------
extern "C" void kernel_launch(void* const* d_in, const int* in_sizes, int n_in,
                              void* d_out, int out_size)
{
    const float* x = (const float*)d_in[0];
    int n = in_sizes[0] / D;
    if (n > MAXN) return;

    EdgeMeta em;
    WPtrs wp;
    const float* b[NET];
    int maxE = 0, totE = 0;
    for (int et = 0; et < NET; et++) {
        em.ef[et]  = (const float*)d_in[1 + 5 * et + 0];
        wp.W[et]   = (const float*)d_in[1 + 5 * et + 1];
        b[et]      = (const float*)d_in[1 + 5 * et + 2];
        em.src[et] = (const int*)  d_in[1 + 5 * et + 3];
        em.dst[et] = (const int*)  d_in[1 + 5 * et + 4];
        em.E[et]   = in_sizes[1 + 5 * et + 3];
        if (em.E[et] > maxE) maxE = em.E[et];
        totE += em.E[et];
    }
    if (totE > CAP_TOTAL) return;
    float* out = (float*)d_out;

    int nelem = NET * n;
    int nblk  = (nelem + G - 1) / G;

    static int smem_bytes = (BM + D) * SAH * (int)sizeof(__half);
    cudaFuncSetAttribute(gemm_epi_kernel,
                         cudaFuncAttributeMaxDynamicSharedMemorySize, smem_bytes);

    // 1) fused prep + count
    {
        int nx = n * D / 8;
        int nw = NET * D * KW;
        int work = nx + nw + totE;
        count_prep_kernel<<<(work + 255) / 256, 256>>>(x, wp, em, n, nx, nw);
    }
    // 2) alloc
    alloc_kernel<<<(nelem + 255) / 256, 256>>>(nelem);
    // 3) fill
    {
        dim3 grid((maxE + 255) / 256, NET);
        fill_kernel<<<grid, 256>>>(em, n);
    }
    // 4) ef-mean, float4 loads (profiled launch)
    efmean_kernel<<<nblk, 256>>>(em, n);
    // 5) x-gather
    gather_kernel<<<nblk, 256>>>(n);
    // 6) fused GEMM + epilogue + reset
    {
        int blocks = (n + BM - 1) / BM;
        gemm_epi_kernel<<<blocks, 256, smem_bytes>>>(
            x, b[0], b[1], b[2], b[3], b[4], out, n);
    }
}